// round 3
// baseline (speedup 1.0000x reference)
#include <cuda_runtime.h>
#include <cuda_bf16.h>
#include <math.h>

// Model dims
#define BB 4
#define SS 1024
#define VV 32000
#define DD 1024
#define HH 16
#define HD 64
#define LL 8
#define FF_DIM 4096
#define NTOK (BB * SS)   // 4096

// ---------------- scratch (device globals; no allocation) ----------------
__device__ float g_x[NTOK * DD];        // residual stream
__device__ float g_ln[NTOK * DD];       // layernorm output
__device__ float g_qkv[NTOK * 3 * DD];  // qkv projection
__device__ float g_attn[NTOK * DD];     // attention output
__device__ float g_ff[NTOK * FF_DIM];   // MLP hidden

// ---------------- embedding: x = tok_emb[idx] + pos_emb ----------------
__global__ __launch_bounds__(256) void embed_kernel(
    const int* __restrict__ idx, const float* __restrict__ tok,
    const float* __restrict__ pos, float* __restrict__ x)
{
    int t = blockIdx.x;            // token 0..4095
    int s = t & (SS - 1);
    int token = idx[t];
    const float* te = tok + (size_t)token * DD;
    const float* pe = pos + (size_t)s * DD;
    float* xr = x + (size_t)t * DD;
    for (int d = threadIdx.x; d < DD; d += 256) xr[d] = te[d] + pe[d];
}

// ---------------- layernorm (one block per row of 1024) ----------------
__global__ __launch_bounds__(256) void ln_kernel(
    const float* __restrict__ x, const float* __restrict__ gw,
    const float* __restrict__ bw, float* __restrict__ y)
{
    __shared__ float rs[8], rq[8];
    int row = blockIdx.x;
    const float* xr = x + (size_t)row * DD;
    float v[4];
    float sum = 0.f, sq = 0.f;
#pragma unroll
    for (int i = 0; i < 4; i++) {
        v[i] = xr[threadIdx.x + i * 256];
        sum += v[i];
        sq += v[i] * v[i];
    }
#pragma unroll
    for (int o = 16; o; o >>= 1) {
        sum += __shfl_xor_sync(0xffffffffu, sum, o);
        sq  += __shfl_xor_sync(0xffffffffu, sq, o);
    }
    int warp = threadIdx.x >> 5;
    if ((threadIdx.x & 31) == 0) { rs[warp] = sum; rq[warp] = sq; }
    __syncthreads();
    float ts = 0.f, tq = 0.f;
#pragma unroll
    for (int w = 0; w < 8; w++) { ts += rs[w]; tq += rq[w]; }
    float mu = ts * (1.f / DD);
    float var = tq * (1.f / DD) - mu * mu;
    float inv = rsqrtf(var + 1e-5f);
    float* yr = y + (size_t)row * DD;
#pragma unroll
    for (int i = 0; i < 4; i++) {
        int d = threadIdx.x + i * 256;
        yr[d] = (v[i] - mu) * inv * gw[d] + bw[d];
    }
}

// ---------------- fp32 tiled GEMM: C = A[M,K] @ B[N,K]^T (+bias)(+silu)(+res) ----------------
// 128x128 tile, BK=8, 256 threads, 8x8 per thread.
__global__ __launch_bounds__(256) void gemm_kernel(
    const float* __restrict__ A, const float* __restrict__ B,
    const float* __restrict__ bias, const float* __restrict__ res,
    float* __restrict__ C, int M, int N, int K, int act_silu)
{
    __shared__ float As[8][128];
    __shared__ float Bs[8][128];
    const int m0 = blockIdx.x * 128;
    const int n0 = blockIdx.y * 128;
    const int tid = threadIdx.x;
    const int tx = tid & 15;
    const int ty = tid >> 4;
    const int lr = tid >> 1;        // 0..127
    const int lc = (tid & 1) * 4;   // 0 or 4
    const float* Ap = A + (size_t)(m0 + lr) * K + lc;
    const float* Bp = B + (size_t)(n0 + lr) * K + lc;

    float acc[8][8];
#pragma unroll
    for (int i = 0; i < 8; i++)
#pragma unroll
        for (int j = 0; j < 8; j++) acc[i][j] = 0.f;

    for (int k0 = 0; k0 < K; k0 += 8) {
        float4 av = *(const float4*)(Ap + k0);
        float4 bv = *(const float4*)(Bp + k0);
        As[lc + 0][lr] = av.x; As[lc + 1][lr] = av.y;
        As[lc + 2][lr] = av.z; As[lc + 3][lr] = av.w;
        Bs[lc + 0][lr] = bv.x; Bs[lc + 1][lr] = bv.y;
        Bs[lc + 2][lr] = bv.z; Bs[lc + 3][lr] = bv.w;
        __syncthreads();
#pragma unroll
        for (int k = 0; k < 8; k++) {
            float a[8], b[8];
            float4 a0 = *(const float4*)&As[k][ty * 8];
            float4 a1 = *(const float4*)&As[k][ty * 8 + 4];
            float4 b0 = *(const float4*)&Bs[k][tx * 8];
            float4 b1 = *(const float4*)&Bs[k][tx * 8 + 4];
            a[0] = a0.x; a[1] = a0.y; a[2] = a0.z; a[3] = a0.w;
            a[4] = a1.x; a[5] = a1.y; a[6] = a1.z; a[7] = a1.w;
            b[0] = b0.x; b[1] = b0.y; b[2] = b0.z; b[3] = b0.w;
            b[4] = b1.x; b[5] = b1.y; b[6] = b1.z; b[7] = b1.w;
#pragma unroll
            for (int i = 0; i < 8; i++)
#pragma unroll
                for (int j = 0; j < 8; j++) acc[i][j] = fmaf(a[i], b[j], acc[i][j]);
        }
        __syncthreads();
    }

#pragma unroll
    for (int i = 0; i < 8; i++) {
        int m = m0 + ty * 8 + i;
#pragma unroll
        for (int j = 0; j < 8; j++) {
            int n = n0 + tx * 8 + j;
            float v = acc[i][j];
            if (bias) v += bias[n];
            if (act_silu) v = v / (1.f + __expf(-v));
            if (res) v += res[(size_t)m * N + n];
            C[(size_t)m * N + n] = v;
        }
    }
}

// ---------------- causal flash attention ----------------
// grid: (S/64 qtiles, H, B). 256 threads = 64 query-groups x 4 lanes.
// Each group of 4 lanes owns one query; each lane owns 16 of 64 head dims.
__global__ __launch_bounds__(256) void attn_kernel(
    const float* __restrict__ qkv, float* __restrict__ o)
{
    __shared__ float Ks[64][64];
    __shared__ float Vs[64][64];
    const int qt = blockIdx.x;
    const int h  = blockIdx.y;
    const int b  = blockIdx.z;
    const int tid = threadIdx.x;
    const int grp = tid >> 2;   // 0..63: query within tile
    const int quad = tid & 3;   // dim quarter
    const int q = qt * 64 + grp;
    const size_t tq = (size_t)(b * SS + q);

    const float* qp = qkv + tq * (3 * DD) + h * (3 * HD) + quad * 16;
    float qf[16];
#pragma unroll
    for (int i = 0; i < 16; i++) qf[i] = qp[i];

    float acc[16];
#pragma unroll
    for (int i = 0; i < 16; i++) acc[i] = 0.f;
    float mval = -1e30f, lval = 0.f;

    for (int kt = 0; kt <= qt; kt++) {
        for (int e = tid; e < 64 * 64; e += 256) {
            int r = e >> 6, c = e & 63;
            const float* base = qkv + (size_t)(b * SS + kt * 64 + r) * (3 * DD) + h * (3 * HD);
            Ks[r][c] = base[HD + c];
            Vs[r][c] = base[2 * HD + c];
        }
        __syncthreads();
#pragma unroll 1
        for (int j = 0; j < 64; j++) {
            float s = 0.f;
#pragma unroll
            for (int i = 0; i < 16; i++) s = fmaf(qf[i], Ks[j][quad * 16 + i], s);
            s += __shfl_xor_sync(0xffffffffu, s, 1);
            s += __shfl_xor_sync(0xffffffffu, s, 2);
            if (kt * 64 + j <= q) {
                s *= 0.125f;  // HD^-0.5
                float mn = fmaxf(mval, s);
                float f = __expf(mval - mn);
                float p = __expf(s - mn);
                lval = lval * f + p;
#pragma unroll
                for (int i = 0; i < 16; i++)
                    acc[i] = fmaf(p, Vs[j][quad * 16 + i], acc[i] * f);
                mval = mn;
            }
        }
        __syncthreads();
    }
    float inv = 1.f / lval;
    float* op = o + tq * DD + h * HD + quad * 16;
#pragma unroll
    for (int i = 0; i < 16; i++) op[i] = acc[i] * inv;
}

// ---------------- launch ----------------
extern "C" void kernel_launch(void* const* d_in, const int* in_sizes, int n_in,
                              void* d_out, int out_size)
{
    const int*   idx     = (const int*)d_in[0];
    const float* tok_emb = (const float*)d_in[1];
    const float* pos_emb = (const float*)d_in[2];
    const float* qkv_w   = (const float*)d_in[3];
    const float* proj_w  = (const float*)d_in[4];
    const float* proj_b  = (const float*)d_in[5];
    const float* ln1_g   = (const float*)d_in[6];
    const float* ln1_b   = (const float*)d_in[7];
    const float* ln2_g   = (const float*)d_in[8];
    const float* ln2_b   = (const float*)d_in[9];
    const float* w1      = (const float*)d_in[10];
    const float* b1      = (const float*)d_in[11];
    const float* w2      = (const float*)d_in[12];
    const float* b2      = (const float*)d_in[13];
    const float* lnf_g   = (const float*)d_in[14];
    const float* lnf_b   = (const float*)d_in[15];
    const float* head_w  = (const float*)d_in[16];
    const float* head_b  = (const float*)d_in[17];
    float* out = (float*)d_out;

    float *x, *ln, *qkvb, *attn, *ff;
    cudaGetSymbolAddress((void**)&x, g_x);
    cudaGetSymbolAddress((void**)&ln, g_ln);
    cudaGetSymbolAddress((void**)&qkvb, g_qkv);
    cudaGetSymbolAddress((void**)&attn, g_attn);
    cudaGetSymbolAddress((void**)&ff, g_ff);

    embed_kernel<<<NTOK, 256>>>(idx, tok_emb, pos_emb, x);

    for (int l = 0; l < LL; l++) {
        // ln1 -> qkv
        ln_kernel<<<NTOK, 256>>>(x, ln1_g + l * DD, ln1_b + l * DD, ln);
        gemm_kernel<<<dim3(NTOK / 128, (3 * DD) / 128), 256>>>(
            ln, qkv_w + (size_t)l * 3 * DD * DD, nullptr, nullptr, qkvb,
            NTOK, 3 * DD, DD, 0);
        // attention
        attn_kernel<<<dim3(SS / 64, HH, BB), 256>>>(qkvb, attn);
        // proj + residual
        gemm_kernel<<<dim3(NTOK / 128, DD / 128), 256>>>(
            attn, proj_w + (size_t)l * DD * DD, proj_b + l * DD, x, x,
            NTOK, DD, DD, 0);
        // ln2 -> MLP
        ln_kernel<<<NTOK, 256>>>(x, ln2_g + l * DD, ln2_b + l * DD, ln);
        gemm_kernel<<<dim3(NTOK / 128, FF_DIM / 128), 256>>>(
            ln, w1 + (size_t)l * FF_DIM * DD, b1 + l * FF_DIM, nullptr, ff,
            NTOK, FF_DIM, DD, 1);
        gemm_kernel<<<dim3(NTOK / 128, DD / 128), 256>>>(
            ff, w2 + (size_t)l * DD * FF_DIM, b2 + l * DD, x, x,
            NTOK, DD, FF_DIM, 0);
    }

    // final LN + LM head
    ln_kernel<<<NTOK, 256>>>(x, lnf_g, lnf_b, ln);
    gemm_kernel<<<dim3(NTOK / 128, VV / 128), 256>>>(
        ln, head_w, head_b, nullptr, out, NTOK, VV, DD, 0);
}

// round 5
// speedup vs baseline: 1.9401x; 1.9401x over previous
#include <cuda_runtime.h>
#include <cuda_bf16.h>
#include <math.h>
#include <stdint.h>

// Model dims
#define BB 4
#define SS 1024
#define VV 32000
#define DD 1024
#define HH 16
#define HD 64
#define LL 8
#define FF_DIM 4096
#define NTOK (BB * SS)   // 4096

// Weight element counts / offsets inside the big split buffers
#define NQKV   25165824   // 8*3072*1024
#define NPROJ  8388608    // 8*1024*1024
#define NW1    33554432   // 8*4096*1024
#define NW2    33554432   // 8*1024*4096
#define NHEAD  32768000   // 32000*1024
#define OFF_QKV  0
#define OFF_PROJ 25165824
#define OFF_W1   33554432
#define OFF_W2   67108864
#define OFF_HEAD 100663296
#define TOTW     133431296

#define SMEM_GEMM 132096   // 1024 align slack + 2 stages * 64KB

// ---------------- scratch (device globals; no allocation) ----------------
__device__ float g_x[NTOK * DD];          // residual stream (fp32)
__device__ float g_qkv[NTOK * 3 * DD];    // qkv projection (fp32, attn input)
__device__ __nv_bfloat16 g_lnh[NTOK * DD], g_lnl[NTOK * DD];
__device__ __nv_bfloat16 g_ah [NTOK * DD], g_al [NTOK * DD];
__device__ __nv_bfloat16 g_ffh[NTOK * FF_DIM], g_ffl[NTOK * FF_DIM];
__device__ __nv_bfloat16 g_wh[TOTW], g_wl[TOTW];

// ---------------- PTX helpers (baseline ISA only; no 'a' features) ----------------
__device__ __forceinline__ uint32_t smem_u32(const void* p) {
    uint32_t a;
    asm("{ .reg .u64 t; cvta.to.shared.u64 t, %1; cvt.u32.u64 %0, t; }" : "=r"(a) : "l"(p));
    return a;
}
__device__ __forceinline__ void cp16(uint32_t s, const void* g) {
    asm volatile("cp.async.cg.shared.global [%0], [%1], 16;" :: "r"(s), "l"(g) : "memory");
}
__device__ __forceinline__ void cp_commit() { asm volatile("cp.async.commit_group;" ::: "memory"); }
__device__ __forceinline__ void cp_wait0()  { asm volatile("cp.async.wait_group 0;" ::: "memory"); }

__device__ __forceinline__ void ldsm4(uint32_t addr, uint32_t* r) {
    asm volatile("ldmatrix.sync.aligned.m8n8.x4.shared.b16 {%0,%1,%2,%3}, [%4];"
        : "=r"(r[0]), "=r"(r[1]), "=r"(r[2]), "=r"(r[3]) : "r"(addr));
}
__device__ __forceinline__ void mma16816(float* c, const uint32_t* a, uint32_t b0, uint32_t b1) {
    asm volatile(
        "mma.sync.aligned.m16n8k16.row.col.f32.bf16.bf16.f32 "
        "{%0,%1,%2,%3}, {%4,%5,%6,%7}, {%8,%9}, {%0,%1,%2,%3};"
        : "+f"(c[0]), "+f"(c[1]), "+f"(c[2]), "+f"(c[3])
        : "r"(a[0]), "r"(a[1]), "r"(a[2]), "r"(a[3]), "r"(b0), "r"(b1));
}
__device__ __forceinline__ uint32_t swz(uint32_t off) { return off ^ ((off >> 3) & 0x70); }

__device__ __forceinline__ uint32_t pk2(__nv_bfloat16 a, __nv_bfloat16 b) {
    return (uint32_t)__bfloat16_as_ushort(a) | ((uint32_t)__bfloat16_as_ushort(b) << 16);
}

// ---------------- weight split: fp32 -> (hi, lo) bf16 ----------------
__global__ __launch_bounds__(256) void split_kernel(
    const float4* __restrict__ w, uint2* __restrict__ h, uint2* __restrict__ l, int n4)
{
    int i = blockIdx.x * 256 + threadIdx.x;
    if (i >= n4) return;
    float4 v = w[i];
    __nv_bfloat16 h0 = __float2bfloat16(v.x), h1 = __float2bfloat16(v.y);
    __nv_bfloat16 h2 = __float2bfloat16(v.z), h3 = __float2bfloat16(v.w);
    __nv_bfloat16 l0 = __float2bfloat16(v.x - __bfloat162float(h0));
    __nv_bfloat16 l1 = __float2bfloat16(v.y - __bfloat162float(h1));
    __nv_bfloat16 l2 = __float2bfloat16(v.z - __bfloat162float(h2));
    __nv_bfloat16 l3 = __float2bfloat16(v.w - __bfloat162float(h3));
    uint2 hv, lv;
    hv.x = pk2(h0, h1); hv.y = pk2(h2, h3);
    lv.x = pk2(l0, l1); lv.y = pk2(l2, l3);
    h[i] = hv; l[i] = lv;
}

// ---------------- embedding ----------------
__global__ __launch_bounds__(256) void embed_kernel(
    const int* __restrict__ idx, const float* __restrict__ tok,
    const float* __restrict__ pos, float* __restrict__ x)
{
    int t = blockIdx.x;
    int s = t & (SS - 1);
    int token = idx[t];
    const float* te = tok + (size_t)token * DD;
    const float* pe = pos + (size_t)s * DD;
    float* xr = x + (size_t)t * DD;
    for (int d = threadIdx.x; d < DD; d += 256) xr[d] = te[d] + pe[d];
}

// ---------------- layernorm -> split bf16 hi/lo ----------------
__global__ __launch_bounds__(256) void ln_kernel(
    const float* __restrict__ x, const float* __restrict__ gw,
    const float* __restrict__ bw, __nv_bfloat16* __restrict__ yh,
    __nv_bfloat16* __restrict__ yl)
{
    __shared__ float rs[8], rq[8];
    int row = blockIdx.x;
    const float* xr = x + (size_t)row * DD;
    float v[4];
    float sum = 0.f, sq = 0.f;
#pragma unroll
    for (int i = 0; i < 4; i++) {
        v[i] = xr[threadIdx.x + i * 256];
        sum += v[i];
        sq += v[i] * v[i];
    }
#pragma unroll
    for (int o = 16; o; o >>= 1) {
        sum += __shfl_xor_sync(0xffffffffu, sum, o);
        sq  += __shfl_xor_sync(0xffffffffu, sq, o);
    }
    int warp = threadIdx.x >> 5;
    if ((threadIdx.x & 31) == 0) { rs[warp] = sum; rq[warp] = sq; }
    __syncthreads();
    float ts = 0.f, tq = 0.f;
#pragma unroll
    for (int w = 0; w < 8; w++) { ts += rs[w]; tq += rq[w]; }
    float mu = ts * (1.f / DD);
    float var = tq * (1.f / DD) - mu * mu;
    float inv = rsqrtf(var + 1e-5f);
#pragma unroll
    for (int i = 0; i < 4; i++) {
        int d = threadIdx.x + i * 256;
        float y = (v[i] - mu) * inv * gw[d] + bw[d];
        __nv_bfloat16 h = __float2bfloat16(y);
        yh[(size_t)row * DD + d] = h;
        yl[(size_t)row * DD + d] = __float2bfloat16(y - __bfloat162float(h));
    }
}

// ---------------- mma.sync split-3 GEMM ----------------
// C[M,N] = (Ah+Al)[M,K] @ (Bh+Bl)[N,K]^T (dropping Al*Bl)
// 128x128 CTA tile, BK=64, 8 warps (2m x 4n), warp tile 64x32,
// double-buffered cp.async, register accumulators, HMMA.16816.
__global__ __launch_bounds__(256, 1) void gemm_tc(
    const __nv_bfloat16* __restrict__ Ah, const __nv_bfloat16* __restrict__ Al,
    const __nv_bfloat16* __restrict__ Bh, const __nv_bfloat16* __restrict__ Bl,
    const float* __restrict__ bias, const float* __restrict__ res,
    float* __restrict__ Cf, __nv_bfloat16* __restrict__ Ch, __nv_bfloat16* __restrict__ Cl,
    int M, int N, int K, int silu)
{
    extern __shared__ char smem[];
    const int tid = threadIdx.x;
    const int wid = tid >> 5;
    const int lane = tid & 31;
    const int m0 = blockIdx.x * 128;
    const int n0 = blockIdx.y * 128;
    const int wm = wid & 1;        // 0..1  (64 rows each)
    const int wn = wid >> 1;       // 0..3  (32 cols each)

    uint32_t sbase = smem_u32(smem);
    uint32_t tiles = (sbase + 1023) & ~1023u;

    // cp.async load slots: 4 units x 16B per 16KB tile
    uint32_t swo[4];
    const char *gA[4], *gAl[4], *gB[4], *gBl[4];
#pragma unroll
    for (int u = 0; u < 4; u++) {
        int unit = tid + u * 256;            // 0..1023
        int row = unit >> 3;                 // 0..127
        int cb = (unit & 7) * 16;            // byte within 128B row
        swo[u] = swz((uint32_t)(row * 128 + cb));
        gA[u]  = (const char*)Ah + ((size_t)(m0 + row) * K) * 2 + cb;
        gAl[u] = (const char*)Al + ((size_t)(m0 + row) * K) * 2 + cb;
        gB[u]  = (const char*)Bh + ((size_t)(n0 + row) * K) * 2 + cb;
        gBl[u] = (const char*)Bl + ((size_t)(n0 + row) * K) * 2 + cb;
    }

    // ldmatrix lane geometry
    const int lr8  = lane & 7;
    const int radd = ((lane >> 3) & 1) * 8;
    const int cadd = (lane >> 4) * 16;
    const int arow = wm * 64 + lr8 + radd;   // + mi*16
    const int brow = wn * 32 + lr8 + radd;   // + n2*16

    float acc[64];
#pragma unroll
    for (int i = 0; i < 64; i++) acc[i] = 0.f;

    const int nk = K >> 6;

    // prologue: chunk 0 -> stage 0
    {
        uint32_t st = tiles;
#pragma unroll
        for (int u = 0; u < 4; u++) {
            cp16(st + swo[u],          gA[u]);
            cp16(st + 16384 + swo[u],  gAl[u]);
            cp16(st + 32768 + swo[u],  gB[u]);
            cp16(st + 49152 + swo[u],  gBl[u]);
        }
        cp_commit(); cp_wait0();
    }
    __syncthreads();

    for (int kc = 0; kc < nk; kc++) {
        int b = kc & 1;
        uint32_t st = tiles + (uint32_t)b * 65536;

        // issue next chunk into the other stage BEFORE compute (overlap)
        if (kc + 1 < nk) {
            uint32_t st2 = tiles + (uint32_t)(b ^ 1) * 65536;
            size_t koff = (size_t)(kc + 1) * 128;   // 64 bf16 = 128 bytes
#pragma unroll
            for (int u = 0; u < 4; u++) {
                cp16(st2 + swo[u],          gA[u] + koff);
                cp16(st2 + 16384 + swo[u],  gAl[u] + koff);
                cp16(st2 + 32768 + swo[u],  gB[u] + koff);
                cp16(st2 + 49152 + swo[u],  gBl[u] + koff);
            }
            cp_commit();
        }

        uint32_t stA = st, stAl = st + 16384, stB = st + 32768, stBl = st + 49152;
#pragma unroll
        for (int ks = 0; ks < 4; ks++) {
            int cb = ks * 32 + cadd;
            uint32_t a4[4][4], bh4[2][4], bl4[2][4];
#pragma unroll
            for (int mi = 0; mi < 4; mi++)
                ldsm4(stA + swz((uint32_t)((arow + mi * 16) * 128 + cb)), a4[mi]);
#pragma unroll
            for (int n2 = 0; n2 < 2; n2++) {
                uint32_t o = swz((uint32_t)((brow + n2 * 16) * 128 + cb));
                ldsm4(stB + o, bh4[n2]);
                ldsm4(stBl + o, bl4[n2]);
            }
            // Ah*Bh + Ah*Bl
#pragma unroll
            for (int mi = 0; mi < 4; mi++)
#pragma unroll
                for (int ni = 0; ni < 4; ni++) {
                    float* cc = &acc[(mi * 4 + ni) * 4];
                    mma16816(cc, a4[mi], bh4[ni >> 1][ni & 1], bh4[ni >> 1][(ni & 1) + 2]);
                    mma16816(cc, a4[mi], bl4[ni >> 1][ni & 1], bl4[ni >> 1][(ni & 1) + 2]);
                }
            // Al*Bh (reuse a4 regs)
#pragma unroll
            for (int mi = 0; mi < 4; mi++)
                ldsm4(stAl + swz((uint32_t)((arow + mi * 16) * 128 + cb)), a4[mi]);
#pragma unroll
            for (int mi = 0; mi < 4; mi++)
#pragma unroll
                for (int ni = 0; ni < 4; ni++)
                    mma16816(&acc[(mi * 4 + ni) * 4], a4[mi],
                             bh4[ni >> 1][ni & 1], bh4[ni >> 1][(ni & 1) + 2]);
        }

        if (kc + 1 < nk) cp_wait0();
        __syncthreads();
    }

    // ---------------- epilogue from register accumulators ----------------
    const int r  = lane >> 2;
    const int c2 = (lane & 3) * 2;
#pragma unroll
    for (int mi = 0; mi < 4; mi++) {
#pragma unroll
        for (int ni = 0; ni < 4; ni++) {
            float* cc = &acc[(mi * 4 + ni) * 4];
            int col = n0 + wn * 32 + ni * 8 + c2;
#pragma unroll
            for (int half = 0; half < 2; half++) {
                int m = m0 + wm * 64 + mi * 16 + r + half * 8;
                float v0 = cc[half * 2], v1 = cc[half * 2 + 1];
                if (bias) { v0 += bias[col]; v1 += bias[col + 1]; }
                if (silu) {
                    v0 = v0 / (1.f + __expf(-v0));
                    v1 = v1 / (1.f + __expf(-v1));
                }
                if (res) {
                    v0 += res[(size_t)m * N + col];
                    v1 += res[(size_t)m * N + col + 1];
                }
                if (Cf) *(float2*)(Cf + (size_t)m * N + col) = make_float2(v0, v1);
                if (Ch) {
                    __nv_bfloat16 h0 = __float2bfloat16(v0);
                    __nv_bfloat16 h1 = __float2bfloat16(v1);
                    __nv_bfloat16 l0 = __float2bfloat16(v0 - __bfloat162float(h0));
                    __nv_bfloat16 l1 = __float2bfloat16(v1 - __bfloat162float(h1));
                    *(uint32_t*)(Ch + (size_t)m * N + col) = pk2(h0, h1);
                    *(uint32_t*)(Cl + (size_t)m * N + col) = pk2(l0, l1);
                }
            }
        }
    }
}

// ---------------- causal flash attention (fp32, outputs split bf16) ----------------
__global__ __launch_bounds__(256) void attn_kernel(
    const float* __restrict__ qkv,
    __nv_bfloat16* __restrict__ oh, __nv_bfloat16* __restrict__ ol)
{
    __shared__ float Ks[64][64];
    __shared__ float Vs[64][64];
    const int qt = blockIdx.x;
    const int h  = blockIdx.y;
    const int b  = blockIdx.z;
    const int tid = threadIdx.x;
    const int grp = tid >> 2;
    const int quad = tid & 3;
    const int q = qt * 64 + grp;
    const size_t tq = (size_t)(b * SS + q);

    const float* qp = qkv + tq * (3 * DD) + h * (3 * HD) + quad * 16;
    float qf[16];
#pragma unroll
    for (int i = 0; i < 16; i++) qf[i] = qp[i];

    float acc[16];
#pragma unroll
    for (int i = 0; i < 16; i++) acc[i] = 0.f;
    float mval = -1e30f, lval = 0.f;

    for (int kt = 0; kt <= qt; kt++) {
        for (int e = tid; e < 64 * 64; e += 256) {
            int rr = e >> 6, cc = e & 63;
            const float* base = qkv + (size_t)(b * SS + kt * 64 + rr) * (3 * DD) + h * (3 * HD);
            Ks[rr][cc] = base[HD + cc];
            Vs[rr][cc] = base[2 * HD + cc];
        }
        __syncthreads();
#pragma unroll 1
        for (int j = 0; j < 64; j++) {
            float s = 0.f;
#pragma unroll
            for (int i = 0; i < 16; i++) s = fmaf(qf[i], Ks[j][quad * 16 + i], s);
            s += __shfl_xor_sync(0xffffffffu, s, 1);
            s += __shfl_xor_sync(0xffffffffu, s, 2);
            if (kt * 64 + j <= q) {
                s *= 0.125f;
                float mn = fmaxf(mval, s);
                float f = __expf(mval - mn);
                float p = __expf(s - mn);
                lval = lval * f + p;
#pragma unroll
                for (int i = 0; i < 16; i++)
                    acc[i] = fmaf(p, Vs[j][quad * 16 + i], acc[i] * f);
                mval = mn;
            }
        }
        __syncthreads();
    }
    float inv = 1.f / lval;
    size_t off = tq * DD + h * HD + quad * 16;
#pragma unroll
    for (int i = 0; i < 16; i++) {
        float vv = acc[i] * inv;
        __nv_bfloat16 hh = __float2bfloat16(vv);
        oh[off + i] = hh;
        ol[off + i] = __float2bfloat16(vv - __bfloat162float(hh));
    }
}

// ---------------- launch ----------------
extern "C" void kernel_launch(void* const* d_in, const int* in_sizes, int n_in,
                              void* d_out, int out_size)
{
    const int*   idx     = (const int*)d_in[0];
    const float* tok_emb = (const float*)d_in[1];
    const float* pos_emb = (const float*)d_in[2];
    const float* qkv_w   = (const float*)d_in[3];
    const float* proj_w  = (const float*)d_in[4];
    const float* proj_b  = (const float*)d_in[5];
    const float* ln1_g   = (const float*)d_in[6];
    const float* ln1_b   = (const float*)d_in[7];
    const float* ln2_g   = (const float*)d_in[8];
    const float* ln2_b   = (const float*)d_in[9];
    const float* w1      = (const float*)d_in[10];
    const float* b1      = (const float*)d_in[11];
    const float* w2      = (const float*)d_in[12];
    const float* b2      = (const float*)d_in[13];
    const float* lnf_g   = (const float*)d_in[14];
    const float* lnf_b   = (const float*)d_in[15];
    const float* head_w  = (const float*)d_in[16];
    const float* head_b  = (const float*)d_in[17];
    float* out = (float*)d_out;

    float *x, *qkvb;
    __nv_bfloat16 *lnh, *lnl, *ah, *al, *ffh, *ffl, *wh, *wl;
    cudaGetSymbolAddress((void**)&x, g_x);
    cudaGetSymbolAddress((void**)&qkvb, g_qkv);
    cudaGetSymbolAddress((void**)&lnh, g_lnh);
    cudaGetSymbolAddress((void**)&lnl, g_lnl);
    cudaGetSymbolAddress((void**)&ah, g_ah);
    cudaGetSymbolAddress((void**)&al, g_al);
    cudaGetSymbolAddress((void**)&ffh, g_ffh);
    cudaGetSymbolAddress((void**)&ffl, g_ffl);
    cudaGetSymbolAddress((void**)&wh, g_wh);
    cudaGetSymbolAddress((void**)&wl, g_wl);

    cudaFuncSetAttribute(gemm_tc, cudaFuncAttributeMaxDynamicSharedMemorySize, SMEM_GEMM);

    // split all weights into bf16 hi/lo (once per forward)
    split_kernel<<<NQKV / 1024, 256>>>((const float4*)qkv_w, (uint2*)(wh + OFF_QKV), (uint2*)(wl + OFF_QKV), NQKV / 4);
    split_kernel<<<NPROJ / 1024, 256>>>((const float4*)proj_w, (uint2*)(wh + OFF_PROJ), (uint2*)(wl + OFF_PROJ), NPROJ / 4);
    split_kernel<<<NW1 / 1024, 256>>>((const float4*)w1, (uint2*)(wh + OFF_W1), (uint2*)(wl + OFF_W1), NW1 / 4);
    split_kernel<<<NW2 / 1024, 256>>>((const float4*)w2, (uint2*)(wh + OFF_W2), (uint2*)(wl + OFF_W2), NW2 / 4);
    split_kernel<<<NHEAD / 1024, 256>>>((const float4*)head_w, (uint2*)(wh + OFF_HEAD), (uint2*)(wl + OFF_HEAD), NHEAD / 4);

    embed_kernel<<<NTOK, 256>>>(idx, tok_emb, pos_emb, x);

    for (int l = 0; l < LL; l++) {
        // ln1 -> qkv (fp32 out for attention)
        ln_kernel<<<NTOK, 256>>>(x, ln1_g + l * DD, ln1_b + l * DD, lnh, lnl);
        gemm_tc<<<dim3(32, 24), 256, SMEM_GEMM>>>(
            lnh, lnl, wh + OFF_QKV + (size_t)l * 3 * DD * DD, wl + OFF_QKV + (size_t)l * 3 * DD * DD,
            nullptr, nullptr, qkvb, nullptr, nullptr, NTOK, 3 * DD, DD, 0);
        // attention -> split output
        attn_kernel<<<dim3(SS / 64, HH, BB), 256>>>(qkvb, ah, al);
        // proj + residual (fp32 x)
        gemm_tc<<<dim3(32, 8), 256, SMEM_GEMM>>>(
            ah, al, wh + OFF_PROJ + (size_t)l * DD * DD, wl + OFF_PROJ + (size_t)l * DD * DD,
            proj_b + l * DD, x, x, nullptr, nullptr, NTOK, DD, DD, 0);
        // ln2 -> MLP
        ln_kernel<<<NTOK, 256>>>(x, ln2_g + l * DD, ln2_b + l * DD, lnh, lnl);
        gemm_tc<<<dim3(32, 32), 256, SMEM_GEMM>>>(
            lnh, lnl, wh + OFF_W1 + (size_t)l * FF_DIM * DD, wl + OFF_W1 + (size_t)l * FF_DIM * DD,
            b1 + l * FF_DIM, nullptr, nullptr, ffh, ffl, NTOK, FF_DIM, DD, 1);
        gemm_tc<<<dim3(32, 8), 256, SMEM_GEMM>>>(
            ffh, ffl, wh + OFF_W2 + (size_t)l * DD * FF_DIM, wl + OFF_W2 + (size_t)l * DD * FF_DIM,
            b2 + l * DD, x, x, nullptr, nullptr, NTOK, DD, FF_DIM, 0);
    }

    // final LN + LM head
    ln_kernel<<<NTOK, 256>>>(x, lnf_g, lnf_b, lnh, lnl);
    gemm_tc<<<dim3(32, VV / 128), 256, SMEM_GEMM>>>(
        lnh, lnl, wh + OFF_HEAD, wl + OFF_HEAD,
        head_b, nullptr, out, nullptr, nullptr, NTOK, VV, DD, 0);
}

// round 8
// speedup vs baseline: 1.9465x; 1.0033x over previous
#include <cuda_runtime.h>
#include <cuda_bf16.h>
#include <math.h>
#include <stdint.h>

// Model dims
#define BB 4
#define SS 1024
#define VV 32000
#define DD 1024
#define HH 16
#define HD 64
#define LL 8
#define FF_DIM 4096
#define NTOK (BB * SS)   // 4096

// Weight element counts / offsets inside the big split buffers
#define NQKV   25165824   // 8*3072*1024
#define NPROJ  8388608    // 8*1024*1024
#define NW1    33554432   // 8*4096*1024
#define NW2    33554432   // 8*1024*4096
#define NHEAD  32768000   // 32000*1024
#define OFF_QKV  0
#define OFF_PROJ 25165824
#define OFF_W1   33554432
#define OFF_W2   67108864
#define OFF_HEAD 100663296
#define TOTW     133431296

// 2 stages * (A 32KB + B 64KB) = 192KB + align slack
#define STAGE_BYTES 98304
#define SMEM_GEMM (1024 + 2 * STAGE_BYTES)

// ---------------- scratch (device globals; no allocation) ----------------
__device__ float g_x[NTOK * DD];          // residual stream (fp32)
__device__ float g_qkv[NTOK * 3 * DD];    // qkv projection (fp32, attn input)
__device__ __nv_bfloat16 g_lnh[NTOK * DD], g_lnl[NTOK * DD];
__device__ __nv_bfloat16 g_ah [NTOK * DD], g_al [NTOK * DD];
__device__ __nv_bfloat16 g_ffh[NTOK * FF_DIM], g_ffl[NTOK * FF_DIM];
__device__ __nv_bfloat16 g_wh[TOTW], g_wl[TOTW];

// ---------------- PTX helpers (baseline ISA only; no 'a' features) ----------------
__device__ __forceinline__ uint32_t smem_u32(const void* p) {
    uint32_t a;
    asm("{ .reg .u64 t; cvta.to.shared.u64 t, %1; cvt.u32.u64 %0, t; }" : "=r"(a) : "l"(p));
    return a;
}
__device__ __forceinline__ void cp16(uint32_t s, const void* g) {
    asm volatile("cp.async.cg.shared.global [%0], [%1], 16;" :: "r"(s), "l"(g) : "memory");
}
__device__ __forceinline__ void cp_commit() { asm volatile("cp.async.commit_group;" ::: "memory"); }
__device__ __forceinline__ void cp_wait0()  { asm volatile("cp.async.wait_group 0;" ::: "memory"); }

__device__ __forceinline__ void ldsm4(uint32_t addr, uint32_t* r) {
    asm volatile("ldmatrix.sync.aligned.m8n8.x4.shared.b16 {%0,%1,%2,%3}, [%4];"
        : "=r"(r[0]), "=r"(r[1]), "=r"(r[2]), "=r"(r[3]) : "r"(addr));
}
__device__ __forceinline__ void mma16816(float* c, const uint32_t* a, uint32_t b0, uint32_t b1) {
    asm volatile(
        "mma.sync.aligned.m16n8k16.row.col.f32.bf16.bf16.f32 "
        "{%0,%1,%2,%3}, {%4,%5,%6,%7}, {%8,%9}, {%0,%1,%2,%3};"
        : "+f"(c[0]), "+f"(c[1]), "+f"(c[2]), "+f"(c[3])
        : "r"(a[0]), "r"(a[1]), "r"(a[2]), "r"(a[3]), "r"(b0), "r"(b1));
}
__device__ __forceinline__ uint32_t swz(uint32_t off) { return off ^ ((off >> 3) & 0x70); }

__device__ __forceinline__ uint32_t pk2(__nv_bfloat16 a, __nv_bfloat16 b) {
    return (uint32_t)__bfloat16_as_ushort(a) | ((uint32_t)__bfloat16_as_ushort(b) << 16);
}

// ---------------- weight split: fp32 -> (hi, lo) bf16 ----------------
__global__ __launch_bounds__(256) void split_kernel(
    const float4* __restrict__ w, uint2* __restrict__ h, uint2* __restrict__ l, int n4)
{
    int i = blockIdx.x * 256 + threadIdx.x;
    if (i >= n4) return;
    float4 v = w[i];
    __nv_bfloat16 h0 = __float2bfloat16(v.x), h1 = __float2bfloat16(v.y);
    __nv_bfloat16 h2 = __float2bfloat16(v.z), h3 = __float2bfloat16(v.w);
    __nv_bfloat16 l0 = __float2bfloat16(v.x - __bfloat162float(h0));
    __nv_bfloat16 l1 = __float2bfloat16(v.y - __bfloat162float(h1));
    __nv_bfloat16 l2 = __float2bfloat16(v.z - __bfloat162float(h2));
    __nv_bfloat16 l3 = __float2bfloat16(v.w - __bfloat162float(h3));
    uint2 hv, lv;
    hv.x = pk2(h0, h1); hv.y = pk2(h2, h3);
    lv.x = pk2(l0, l1); lv.y = pk2(l2, l3);
    h[i] = hv; l[i] = lv;
}

// ---------------- embedding ----------------
__global__ __launch_bounds__(256) void embed_kernel(
    const int* __restrict__ idx, const float* __restrict__ tok,
    const float* __restrict__ pos, float* __restrict__ x)
{
    int t = blockIdx.x;
    int s = t & (SS - 1);
    int token = idx[t];
    const float* te = tok + (size_t)token * DD;
    const float* pe = pos + (size_t)s * DD;
    float* xr = x + (size_t)t * DD;
    for (int d = threadIdx.x; d < DD; d += 256) xr[d] = te[d] + pe[d];
}

// ---------------- layernorm -> split bf16 hi/lo ----------------
__global__ __launch_bounds__(256) void ln_kernel(
    const float* __restrict__ x, const float* __restrict__ gw,
    const float* __restrict__ bw, __nv_bfloat16* __restrict__ yh,
    __nv_bfloat16* __restrict__ yl)
{
    __shared__ float rs[8], rq[8];
    int row = blockIdx.x;
    const float* xr = x + (size_t)row * DD;
    float v[4];
    float sum = 0.f, sq = 0.f;
#pragma unroll
    for (int i = 0; i < 4; i++) {
        v[i] = xr[threadIdx.x + i * 256];
        sum += v[i];
        sq += v[i] * v[i];
    }
#pragma unroll
    for (int o = 16; o; o >>= 1) {
        sum += __shfl_xor_sync(0xffffffffu, sum, o);
        sq  += __shfl_xor_sync(0xffffffffu, sq, o);
    }
    int warp = threadIdx.x >> 5;
    if ((threadIdx.x & 31) == 0) { rs[warp] = sum; rq[warp] = sq; }
    __syncthreads();
    float ts = 0.f, tq = 0.f;
#pragma unroll
    for (int w = 0; w < 8; w++) { ts += rs[w]; tq += rq[w]; }
    float mu = ts * (1.f / DD);
    float var = tq * (1.f / DD) - mu * mu;
    float inv = rsqrtf(var + 1e-5f);
#pragma unroll
    for (int i = 0; i < 4; i++) {
        int d = threadIdx.x + i * 256;
        float y = (v[i] - mu) * inv * gw[d] + bw[d];
        __nv_bfloat16 h = __float2bfloat16(y);
        yh[(size_t)row * DD + d] = h;
        yl[(size_t)row * DD + d] = __float2bfloat16(y - __bfloat162float(h));
    }
}

// ---------------- mma.sync split-3 GEMM ----------------
// C[M,N] = (Ah+Al)[M,K] @ (Bh+Bl)[N,K]^T (dropping Al*Bl)
// CTA tile 128x256, BK=64, 8 warps (2m x 4n), warp tile 64x64,
// double-buffered cp.async, register accumulators (128 f32), HMMA.16816.
__global__ __launch_bounds__(256, 1) void gemm_tc(
    const __nv_bfloat16* __restrict__ Ah, const __nv_bfloat16* __restrict__ Al,
    const __nv_bfloat16* __restrict__ Bh, const __nv_bfloat16* __restrict__ Bl,
    const float* __restrict__ bias, const float* __restrict__ res,
    float* __restrict__ Cf, __nv_bfloat16* __restrict__ Ch, __nv_bfloat16* __restrict__ Cl,
    int M, int N, int K, int silu)
{
    extern __shared__ char smem[];
    const int tid = threadIdx.x;
    const int wid = tid >> 5;
    const int lane = tid & 31;
    const int m0 = blockIdx.x * 128;
    const int n0 = blockIdx.y * 256;
    const int wm = wid & 1;        // 0..1  (64 rows each)
    const int wn = wid >> 1;       // 0..3  (64 cols each)

    uint32_t sbase = smem_u32(smem);
    uint32_t tiles = (sbase + 1023) & ~1023u;
    // stage layout: Ah @0 (16KB), Al @16K, Bh @32K (32KB), Bl @64K (32KB)

    // cp.async load slots
    uint32_t swoA[4];                 // A: 1024 units per tile, 4 per thread
    const char *gA[4], *gAl[4];
    uint32_t swoB[8];                 // B: 2048 units per tile, 8 per thread
    const char *gB[8], *gBl[8];
#pragma unroll
    for (int u = 0; u < 4; u++) {
        int unit = tid + u * 256;
        int row = unit >> 3;
        int cb = (unit & 7) * 16;
        swoA[u] = swz((uint32_t)(row * 128 + cb));
        gA[u]  = (const char*)Ah + ((size_t)(m0 + row) * K) * 2 + cb;
        gAl[u] = (const char*)Al + ((size_t)(m0 + row) * K) * 2 + cb;
    }
#pragma unroll
    for (int u = 0; u < 8; u++) {
        int unit = tid + u * 256;
        int row = unit >> 3;          // 0..255
        int cb = (unit & 7) * 16;
        swoB[u] = swz((uint32_t)(row * 128 + cb));
        gB[u]  = (const char*)Bh + ((size_t)(n0 + row) * K) * 2 + cb;
        gBl[u] = (const char*)Bl + ((size_t)(n0 + row) * K) * 2 + cb;
    }

    // ldmatrix lane geometry
    const int lr8  = lane & 7;
    const int radd = ((lane >> 3) & 1) * 8;
    const int cadd = (lane >> 4) * 16;
    const int arow = wm * 64 + lr8 + radd;   // + mi*16
    const int brow = wn * 64 + lr8 + radd;   // + n2*16

    float acc[128];
#pragma unroll
    for (int i = 0; i < 128; i++) acc[i] = 0.f;

    const int nk = K >> 6;

    // prologue: chunk 0 -> stage 0
    {
        uint32_t st = tiles;
#pragma unroll
        for (int u = 0; u < 4; u++) {
            cp16(st + swoA[u],         gA[u]);
            cp16(st + 16384 + swoA[u], gAl[u]);
        }
#pragma unroll
        for (int u = 0; u < 8; u++) {
            cp16(st + 32768 + swoB[u], gB[u]);
            cp16(st + 65536 + swoB[u], gBl[u]);
        }
        cp_commit(); cp_wait0();
    }
    __syncthreads();

    for (int kc = 0; kc < nk; kc++) {
        int b = kc & 1;
        uint32_t st = tiles + (uint32_t)b * STAGE_BYTES;

        // issue next chunk into the other stage BEFORE compute (overlap)
        if (kc + 1 < nk) {
            uint32_t st2 = tiles + (uint32_t)(b ^ 1) * STAGE_BYTES;
            size_t koff = (size_t)(kc + 1) * 128;   // 64 bf16 = 128 bytes
#pragma unroll
            for (int u = 0; u < 4; u++) {
                cp16(st2 + swoA[u],         gA[u] + koff);
                cp16(st2 + 16384 + swoA[u], gAl[u] + koff);
            }
#pragma unroll
            for (int u = 0; u < 8; u++) {
                cp16(st2 + 32768 + swoB[u], gB[u] + koff);
                cp16(st2 + 65536 + swoB[u], gBl[u] + koff);
            }
            cp_commit();
        }

        uint32_t stA = st, stAl = st + 16384, stB = st + 32768, stBl = st + 65536;
#pragma unroll
        for (int ks = 0; ks < 4; ks++) {
            int cb = ks * 32 + cadd;
            uint32_t a4[4][4], bh4[4][4], bl4[4][4];
#pragma unroll
            for (int mi = 0; mi < 4; mi++)
                ldsm4(stA + swz((uint32_t)((arow + mi * 16) * 128 + cb)), a4[mi]);
#pragma unroll
            for (int n2 = 0; n2 < 4; n2++) {
                uint32_t o = swz((uint32_t)((brow + n2 * 16) * 128 + cb));
                ldsm4(stB + o, bh4[n2]);
                ldsm4(stBl + o, bl4[n2]);
            }
            // Ah*Bh + Ah*Bl
#pragma unroll
            for (int mi = 0; mi < 4; mi++)
#pragma unroll
                for (int ni = 0; ni < 8; ni++) {
                    float* cc = &acc[(mi * 8 + ni) * 4];
                    mma16816(cc, a4[mi], bh4[ni >> 1][ni & 1], bh4[ni >> 1][(ni & 1) + 2]);
                    mma16816(cc, a4[mi], bl4[ni >> 1][ni & 1], bl4[ni >> 1][(ni & 1) + 2]);
                }
            // Al*Bh (reuse a4 regs)
#pragma unroll
            for (int mi = 0; mi < 4; mi++)
                ldsm4(stAl + swz((uint32_t)((arow + mi * 16) * 128 + cb)), a4[mi]);
#pragma unroll
            for (int mi = 0; mi < 4; mi++)
#pragma unroll
                for (int ni = 0; ni < 8; ni++)
                    mma16816(&acc[(mi * 8 + ni) * 4], a4[mi],
                             bh4[ni >> 1][ni & 1], bh4[ni >> 1][(ni & 1) + 2]);
        }

        if (kc + 1 < nk) cp_wait0();
        __syncthreads();
    }

    // ---------------- epilogue from register accumulators ----------------
    const int r  = lane >> 2;
    const int c2 = (lane & 3) * 2;
#pragma unroll
    for (int mi = 0; mi < 4; mi++) {
#pragma unroll
        for (int ni = 0; ni < 8; ni++) {
            float* cc = &acc[(mi * 8 + ni) * 4];
            int col = n0 + wn * 64 + ni * 8 + c2;
#pragma unroll
            for (int half = 0; half < 2; half++) {
                int m = m0 + wm * 64 + mi * 16 + r + half * 8;
                float v0 = cc[half * 2], v1 = cc[half * 2 + 1];
                if (bias) { v0 += bias[col]; v1 += bias[col + 1]; }
                if (silu) {
                    v0 = v0 / (1.f + __expf(-v0));
                    v1 = v1 / (1.f + __expf(-v1));
                }
                if (res) {
                    v0 += res[(size_t)m * N + col];
                    v1 += res[(size_t)m * N + col + 1];
                }
                if (Cf) *(float2*)(Cf + (size_t)m * N + col) = make_float2(v0, v1);
                if (Ch) {
                    __nv_bfloat16 h0 = __float2bfloat16(v0);
                    __nv_bfloat16 h1 = __float2bfloat16(v1);
                    __nv_bfloat16 l0 = __float2bfloat16(v0 - __bfloat162float(h0));
                    __nv_bfloat16 l1 = __float2bfloat16(v1 - __bfloat162float(h1));
                    *(uint32_t*)(Ch + (size_t)m * N + col) = pk2(h0, h1);
                    *(uint32_t*)(Cl + (size_t)m * N + col) = pk2(l0, l1);
                }
            }
        }
    }
}

// ---------------- causal flash attention (fp32, outputs split bf16) ----------------
__global__ __launch_bounds__(256) void attn_kernel(
    const float* __restrict__ qkv,
    __nv_bfloat16* __restrict__ oh, __nv_bfloat16* __restrict__ ol)
{
    __shared__ float Ks[64][64];
    __shared__ float Vs[64][64];
    const int qt = blockIdx.x;
    const int h  = blockIdx.y;
    const int b  = blockIdx.z;
    const int tid = threadIdx.x;
    const int grp = tid >> 2;
    const int quad = tid & 3;
    const int q = qt * 64 + grp;
    const size_t tq = (size_t)(b * SS + q);

    const float* qp = qkv + tq * (3 * DD) + h * (3 * HD) + quad * 16;
    float qf[16];
#pragma unroll
    for (int i = 0; i < 16; i++) qf[i] = qp[i];

    float acc[16];
#pragma unroll
    for (int i = 0; i < 16; i++) acc[i] = 0.f;
    float mval = -1e30f, lval = 0.f;

    for (int kt = 0; kt <= qt; kt++) {
        for (int e = tid; e < 64 * 64; e += 256) {
            int rr = e >> 6, cc = e & 63;
            const float* base = qkv + (size_t)(b * SS + kt * 64 + rr) * (3 * DD) + h * (3 * HD);
            Ks[rr][cc] = base[HD + cc];
            Vs[rr][cc] = base[2 * HD + cc];
        }
        __syncthreads();
#pragma unroll 1
        for (int j = 0; j < 64; j++) {
            float s = 0.f;
#pragma unroll
            for (int i = 0; i < 16; i++) s = fmaf(qf[i], Ks[j][quad * 16 + i], s);
            s += __shfl_xor_sync(0xffffffffu, s, 1);
            s += __shfl_xor_sync(0xffffffffu, s, 2);
            if (kt * 64 + j <= q) {
                s *= 0.125f;
                float mn = fmaxf(mval, s);
                float f = __expf(mval - mn);
                float p = __expf(s - mn);
                lval = lval * f + p;
#pragma unroll
                for (int i = 0; i < 16; i++)
                    acc[i] = fmaf(p, Vs[j][quad * 16 + i], acc[i] * f);
                mval = mn;
            }
        }
        __syncthreads();
    }
    float inv = 1.f / lval;
    size_t off = tq * DD + h * HD + quad * 16;
#pragma unroll
    for (int i = 0; i < 16; i++) {
        float vv = acc[i] * inv;
        __nv_bfloat16 hh = __float2bfloat16(vv);
        oh[off + i] = hh;
        ol[off + i] = __float2bfloat16(vv - __bfloat162float(hh));
    }
}

// ---------------- launch ----------------
extern "C" void kernel_launch(void* const* d_in, const int* in_sizes, int n_in,
                              void* d_out, int out_size)
{
    const int*   idx     = (const int*)d_in[0];
    const float* tok_emb = (const float*)d_in[1];
    const float* pos_emb = (const float*)d_in[2];
    const float* qkv_w   = (const float*)d_in[3];
    const float* proj_w  = (const float*)d_in[4];
    const float* proj_b  = (const float*)d_in[5];
    const float* ln1_g   = (const float*)d_in[6];
    const float* ln1_b   = (const float*)d_in[7];
    const float* ln2_g   = (const float*)d_in[8];
    const float* ln2_b   = (const float*)d_in[9];
    const float* w1      = (const float*)d_in[10];
    const float* b1      = (const float*)d_in[11];
    const float* w2      = (const float*)d_in[12];
    const float* b2      = (const float*)d_in[13];
    const float* lnf_g   = (const float*)d_in[14];
    const float* lnf_b   = (const float*)d_in[15];
    const float* head_w  = (const float*)d_in[16];
    const float* head_b  = (const float*)d_in[17];
    float* out = (float*)d_out;

    float *x, *qkvb;
    __nv_bfloat16 *lnh, *lnl, *ah, *al, *ffh, *ffl, *wh, *wl;
    cudaGetSymbolAddress((void**)&x, g_x);
    cudaGetSymbolAddress((void**)&qkvb, g_qkv);
    cudaGetSymbolAddress((void**)&lnh, g_lnh);
    cudaGetSymbolAddress((void**)&lnl, g_lnl);
    cudaGetSymbolAddress((void**)&ah, g_ah);
    cudaGetSymbolAddress((void**)&al, g_al);
    cudaGetSymbolAddress((void**)&ffh, g_ffh);
    cudaGetSymbolAddress((void**)&ffl, g_ffl);
    cudaGetSymbolAddress((void**)&wh, g_wh);
    cudaGetSymbolAddress((void**)&wl, g_wl);

    cudaFuncSetAttribute(gemm_tc, cudaFuncAttributeMaxDynamicSharedMemorySize, SMEM_GEMM);

    // split all weights into bf16 hi/lo (once per forward)
    split_kernel<<<NQKV / 1024, 256>>>((const float4*)qkv_w, (uint2*)(wh + OFF_QKV), (uint2*)(wl + OFF_QKV), NQKV / 4);
    split_kernel<<<NPROJ / 1024, 256>>>((const float4*)proj_w, (uint2*)(wh + OFF_PROJ), (uint2*)(wl + OFF_PROJ), NPROJ / 4);
    split_kernel<<<NW1 / 1024, 256>>>((const float4*)w1, (uint2*)(wh + OFF_W1), (uint2*)(wl + OFF_W1), NW1 / 4);
    split_kernel<<<NW2 / 1024, 256>>>((const float4*)w2, (uint2*)(wh + OFF_W2), (uint2*)(wl + OFF_W2), NW2 / 4);
    split_kernel<<<NHEAD / 1024, 256>>>((const float4*)head_w, (uint2*)(wh + OFF_HEAD), (uint2*)(wl + OFF_HEAD), NHEAD / 4);

    embed_kernel<<<NTOK, 256>>>(idx, tok_emb, pos_emb, x);

    for (int l = 0; l < LL; l++) {
        // ln1 -> qkv (fp32 out for attention)
        ln_kernel<<<NTOK, 256>>>(x, ln1_g + l * DD, ln1_b + l * DD, lnh, lnl);
        gemm_tc<<<dim3(32, 12), 256, SMEM_GEMM>>>(
            lnh, lnl, wh + OFF_QKV + (size_t)l * 3 * DD * DD, wl + OFF_QKV + (size_t)l * 3 * DD * DD,
            nullptr, nullptr, qkvb, nullptr, nullptr, NTOK, 3 * DD, DD, 0);
        // attention -> split output
        attn_kernel<<<dim3(SS / 64, HH, BB), 256>>>(qkvb, ah, al);
        // proj + residual (fp32 x)
        gemm_tc<<<dim3(32, 4), 256, SMEM_GEMM>>>(
            ah, al, wh + OFF_PROJ + (size_t)l * DD * DD, wl + OFF_PROJ + (size_t)l * DD * DD,
            proj_b + l * DD, x, x, nullptr, nullptr, NTOK, DD, DD, 0);
        // ln2 -> MLP
        ln_kernel<<<NTOK, 256>>>(x, ln2_g + l * DD, ln2_b + l * DD, lnh, lnl);
        gemm_tc<<<dim3(32, 16), 256, SMEM_GEMM>>>(
            lnh, lnl, wh + OFF_W1 + (size_t)l * FF_DIM * DD, wl + OFF_W1 + (size_t)l * FF_DIM * DD,
            b1 + l * FF_DIM, nullptr, nullptr, ffh, ffl, NTOK, FF_DIM, DD, 1);
        gemm_tc<<<dim3(32, 4), 256, SMEM_GEMM>>>(
            ffh, ffl, wh + OFF_W2 + (size_t)l * DD * FF_DIM, wl + OFF_W2 + (size_t)l * DD * FF_DIM,
            b2 + l * DD, x, x, nullptr, nullptr, NTOK, DD, FF_DIM, 0);
    }

    // final LN + LM head
    ln_kernel<<<NTOK, 256>>>(x, lnf_g, lnf_b, lnh, lnl);
    gemm_tc<<<dim3(32, VV / 256), 256, SMEM_GEMM>>>(
        lnh, lnl, wh + OFF_HEAD, wl + OFF_HEAD,
        head_b, nullptr, out, nullptr, nullptr, NTOK, VV, DD, 0);
}

// round 10
// speedup vs baseline: 3.8730x; 1.9897x over previous
#include <cuda_runtime.h>
#include <cuda_bf16.h>
#include <cuda_fp16.h>
#include <math.h>
#include <stdint.h>

// Model dims
#define BB 4
#define SS 1024
#define VV 32000
#define DD 1024
#define HH 16
#define HD 64
#define LL 8
#define FF_DIM 4096
#define NTOK (BB * SS)   // 4096

// Weight element counts / offsets inside the big split buffers
#define NQKV   25165824
#define NPROJ  8388608
#define NW1    33554432
#define NW2    33554432
#define NHEAD  32768000
#define OFF_QKV  0
#define OFF_PROJ 25165824
#define OFF_W1   33554432
#define OFF_W2   67108864
#define OFF_HEAD 100663296
#define TOTW     133431296

#define STAGE_BYTES 98304
#define SMEM_GEMM (1024 + 2 * STAGE_BYTES)

// ---------------- scratch (device globals; no allocation) ----------------
__device__ float g_x[NTOK * DD];          // residual stream (fp32)
__device__ __half g_qkvh[NTOK * 3 * DD];  // qkv projection (fp16, attn input)
__device__ __nv_bfloat16 g_lnh[NTOK * DD], g_lnl[NTOK * DD];
__device__ __nv_bfloat16 g_ah [NTOK * DD], g_al [NTOK * DD];
__device__ __nv_bfloat16 g_ffh[NTOK * FF_DIM], g_ffl[NTOK * FF_DIM];
__device__ __nv_bfloat16 g_wh[TOTW], g_wl[TOTW];

// ---------------- PTX helpers (baseline ISA only) ----------------
__device__ __forceinline__ uint32_t smem_u32(const void* p) {
    uint32_t a;
    asm("{ .reg .u64 t; cvta.to.shared.u64 t, %1; cvt.u32.u64 %0, t; }" : "=r"(a) : "l"(p));
    return a;
}
__device__ __forceinline__ void cp16(uint32_t s, const void* g) {
    asm volatile("cp.async.cg.shared.global [%0], [%1], 16;" :: "r"(s), "l"(g) : "memory");
}
__device__ __forceinline__ void cp_commit() { asm volatile("cp.async.commit_group;" ::: "memory"); }
__device__ __forceinline__ void cp_wait0()  { asm volatile("cp.async.wait_group 0;" ::: "memory"); }

__device__ __forceinline__ void ldsm4(uint32_t addr, uint32_t* r) {
    asm volatile("ldmatrix.sync.aligned.m8n8.x4.shared.b16 {%0,%1,%2,%3}, [%4];"
        : "=r"(r[0]), "=r"(r[1]), "=r"(r[2]), "=r"(r[3]) : "r"(addr));
}
__device__ __forceinline__ void ldsm4t(uint32_t addr, uint32_t* r) {
    asm volatile("ldmatrix.sync.aligned.m8n8.x4.trans.shared.b16 {%0,%1,%2,%3}, [%4];"
        : "=r"(r[0]), "=r"(r[1]), "=r"(r[2]), "=r"(r[3]) : "r"(addr));
}
__device__ __forceinline__ void mma_bf16(float* c, const uint32_t* a, uint32_t b0, uint32_t b1) {
    asm volatile(
        "mma.sync.aligned.m16n8k16.row.col.f32.bf16.bf16.f32 "
        "{%0,%1,%2,%3}, {%4,%5,%6,%7}, {%8,%9}, {%0,%1,%2,%3};"
        : "+f"(c[0]), "+f"(c[1]), "+f"(c[2]), "+f"(c[3])
        : "r"(a[0]), "r"(a[1]), "r"(a[2]), "r"(a[3]), "r"(b0), "r"(b1));
}
__device__ __forceinline__ void mma_f16(float* c, const uint32_t* a, uint32_t b0, uint32_t b1) {
    asm volatile(
        "mma.sync.aligned.m16n8k16.row.col.f32.f16.f16.f32 "
        "{%0,%1,%2,%3}, {%4,%5,%6,%7}, {%8,%9}, {%0,%1,%2,%3};"
        : "+f"(c[0]), "+f"(c[1]), "+f"(c[2]), "+f"(c[3])
        : "r"(a[0]), "r"(a[1]), "r"(a[2]), "r"(a[3]), "r"(b0), "r"(b1));
}
__device__ __forceinline__ uint32_t swz(uint32_t off) { return off ^ ((off >> 3) & 0x70); }

__device__ __forceinline__ uint32_t pk2(__nv_bfloat16 a, __nv_bfloat16 b) {
    return (uint32_t)__bfloat16_as_ushort(a) | ((uint32_t)__bfloat16_as_ushort(b) << 16);
}
__device__ __forceinline__ uint32_t pk2h(float a, float b) {
    __half2 h = __floats2half2_rn(a, b);
    return *(uint32_t*)&h;
}

// ---------------- weight split: fp32 -> (hi, lo) bf16 ----------------
__global__ __launch_bounds__(256) void split_kernel(
    const float4* __restrict__ w, uint2* __restrict__ h, uint2* __restrict__ l, int n4)
{
    int i = blockIdx.x * 256 + threadIdx.x;
    if (i >= n4) return;
    float4 v = w[i];
    __nv_bfloat16 h0 = __float2bfloat16(v.x), h1 = __float2bfloat16(v.y);
    __nv_bfloat16 h2 = __float2bfloat16(v.z), h3 = __float2bfloat16(v.w);
    __nv_bfloat16 l0 = __float2bfloat16(v.x - __bfloat162float(h0));
    __nv_bfloat16 l1 = __float2bfloat16(v.y - __bfloat162float(h1));
    __nv_bfloat16 l2 = __float2bfloat16(v.z - __bfloat162float(h2));
    __nv_bfloat16 l3 = __float2bfloat16(v.w - __bfloat162float(h3));
    uint2 hv, lv;
    hv.x = pk2(h0, h1); hv.y = pk2(h2, h3);
    lv.x = pk2(l0, l1); lv.y = pk2(l2, l3);
    h[i] = hv; l[i] = lv;
}

// ---------------- weight round: fp32 -> single fp16 (head) ----------------
__global__ __launch_bounds__(256) void split_half_kernel(
    const float4* __restrict__ w, uint2* __restrict__ h, int n4)
{
    int i = blockIdx.x * 256 + threadIdx.x;
    if (i >= n4) return;
    float4 v = w[i];
    uint2 hv;
    hv.x = pk2h(v.x, v.y); hv.y = pk2h(v.z, v.w);
    h[i] = hv;
}

// ---------------- embedding ----------------
__global__ __launch_bounds__(256) void embed_kernel(
    const int* __restrict__ idx, const float* __restrict__ tok,
    const float* __restrict__ pos, float* __restrict__ x)
{
    int t = blockIdx.x;
    int s = t & (SS - 1);
    int token = idx[t];
    const float* te = tok + (size_t)token * DD;
    const float* pe = pos + (size_t)s * DD;
    float* xr = x + (size_t)t * DD;
    for (int d = threadIdx.x; d < DD; d += 256) xr[d] = te[d] + pe[d];
}

// ---------------- layernorm -> split hi/lo (bf16 or fp16) ----------------
template<int FP16>
__global__ __launch_bounds__(256) void ln_kernel(
    const float* __restrict__ x, const float* __restrict__ gw,
    const float* __restrict__ bw, __nv_bfloat16* __restrict__ yh,
    __nv_bfloat16* __restrict__ yl)
{
    __shared__ float rs[8], rq[8];
    int row = blockIdx.x;
    const float* xr = x + (size_t)row * DD;
    float v[4];
    float sum = 0.f, sq = 0.f;
#pragma unroll
    for (int i = 0; i < 4; i++) {
        v[i] = xr[threadIdx.x + i * 256];
        sum += v[i];
        sq += v[i] * v[i];
    }
#pragma unroll
    for (int o = 16; o; o >>= 1) {
        sum += __shfl_xor_sync(0xffffffffu, sum, o);
        sq  += __shfl_xor_sync(0xffffffffu, sq, o);
    }
    int warp = threadIdx.x >> 5;
    if ((threadIdx.x & 31) == 0) { rs[warp] = sum; rq[warp] = sq; }
    __syncthreads();
    float ts = 0.f, tq = 0.f;
#pragma unroll
    for (int w = 0; w < 8; w++) { ts += rs[w]; tq += rq[w]; }
    float mu = ts * (1.f / DD);
    float var = tq * (1.f / DD) - mu * mu;
    float inv = rsqrtf(var + 1e-5f);
#pragma unroll
    for (int i = 0; i < 4; i++) {
        int d = threadIdx.x + i * 256;
        float y = (v[i] - mu) * inv * gw[d] + bw[d];
        if (FP16) {
            __half h = __float2half_rn(y);
            ((__half*)yh)[(size_t)row * DD + d] = h;
            ((__half*)yl)[(size_t)row * DD + d] = __float2half_rn(y - __half2float(h));
        } else {
            __nv_bfloat16 h = __float2bfloat16(y);
            yh[(size_t)row * DD + d] = h;
            yl[(size_t)row * DD + d] = __float2bfloat16(y - __bfloat162float(h));
        }
    }
}

// ---------------- mma.sync GEMM ----------------
// M2==0: bf16 3-pass  C = AhBh + AhBl + AlBh
// M2==1: fp16 2-pass  C = AhBh + AlBh   (B single fp16, Bl unused)
// CTA tile 128x256, BK=64, 8 warps (2m x 4n), warp tile 64x64.
template<int M2>
__global__ __launch_bounds__(256, 1) void gemm_tc(
    const __nv_bfloat16* __restrict__ Ah, const __nv_bfloat16* __restrict__ Al,
    const __nv_bfloat16* __restrict__ Bh, const __nv_bfloat16* __restrict__ Bl,
    const float* __restrict__ bias, const float* __restrict__ res,
    float* __restrict__ Cf, __half* __restrict__ Chalf,
    __nv_bfloat16* __restrict__ Ch, __nv_bfloat16* __restrict__ Cl,
    int M, int N, int K, int silu)
{
    extern __shared__ char smem[];
    const int tid = threadIdx.x;
    const int wid = tid >> 5;
    const int lane = tid & 31;
    const int m0 = blockIdx.x * 128;
    const int n0 = blockIdx.y * 256;
    const int wm = wid & 1;
    const int wn = wid >> 1;

    uint32_t sbase = smem_u32(smem);
    uint32_t tiles = (sbase + 1023) & ~1023u;
    // stage: Ah @0 (16KB), Al @16K, Bh @32K (32KB), Bl @64K (32KB, M2==0 only)

    uint32_t swoA[4];
    const char *gA[4], *gAl[4];
    uint32_t swoB[8];
    const char *gB[8], *gBl[8];
#pragma unroll
    for (int u = 0; u < 4; u++) {
        int unit = tid + u * 256;
        int row = unit >> 3;
        int cb = (unit & 7) * 16;
        swoA[u] = swz((uint32_t)(row * 128 + cb));
        gA[u]  = (const char*)Ah + ((size_t)(m0 + row) * K) * 2 + cb;
        gAl[u] = (const char*)Al + ((size_t)(m0 + row) * K) * 2 + cb;
    }
#pragma unroll
    for (int u = 0; u < 8; u++) {
        int unit = tid + u * 256;
        int row = unit >> 3;
        int cb = (unit & 7) * 16;
        swoB[u] = swz((uint32_t)(row * 128 + cb));
        gB[u]  = (const char*)Bh + ((size_t)(n0 + row) * K) * 2 + cb;
        gBl[u] = (const char*)Bl + ((size_t)(n0 + row) * K) * 2 + cb;
    }

    const int lr8  = lane & 7;
    const int radd = ((lane >> 3) & 1) * 8;
    const int cadd = (lane >> 4) * 16;
    const int arow = wm * 64 + lr8 + radd;
    const int brow = wn * 64 + lr8 + radd;

    float acc[128];
#pragma unroll
    for (int i = 0; i < 128; i++) acc[i] = 0.f;

    const int nk = K >> 6;

    {
        uint32_t st = tiles;
#pragma unroll
        for (int u = 0; u < 4; u++) {
            cp16(st + swoA[u],         gA[u]);
            cp16(st + 16384 + swoA[u], gAl[u]);
        }
#pragma unroll
        for (int u = 0; u < 8; u++) {
            cp16(st + 32768 + swoB[u], gB[u]);
            if (M2 == 0) cp16(st + 65536 + swoB[u], gBl[u]);
        }
        cp_commit(); cp_wait0();
    }
    __syncthreads();

    for (int kc = 0; kc < nk; kc++) {
        int b = kc & 1;
        uint32_t st = tiles + (uint32_t)b * STAGE_BYTES;

        if (kc + 1 < nk) {
            uint32_t st2 = tiles + (uint32_t)(b ^ 1) * STAGE_BYTES;
            size_t koff = (size_t)(kc + 1) * 128;
#pragma unroll
            for (int u = 0; u < 4; u++) {
                cp16(st2 + swoA[u],         gA[u] + koff);
                cp16(st2 + 16384 + swoA[u], gAl[u] + koff);
            }
#pragma unroll
            for (int u = 0; u < 8; u++) {
                cp16(st2 + 32768 + swoB[u], gB[u] + koff);
                if (M2 == 0) cp16(st2 + 65536 + swoB[u], gBl[u] + koff);
            }
            cp_commit();
        }

        uint32_t stA = st, stAl = st + 16384, stB = st + 32768, stBl = st + 65536;
#pragma unroll
        for (int ks = 0; ks < 4; ks++) {
            int cb = ks * 32 + cadd;
            uint32_t a4[4][4], bh4[4][4], bl4[4][4];
#pragma unroll
            for (int mi = 0; mi < 4; mi++)
                ldsm4(stA + swz((uint32_t)((arow + mi * 16) * 128 + cb)), a4[mi]);
#pragma unroll
            for (int n2 = 0; n2 < 4; n2++) {
                uint32_t o = swz((uint32_t)((brow + n2 * 16) * 128 + cb));
                ldsm4(stB + o, bh4[n2]);
                if (M2 == 0) ldsm4(stBl + o, bl4[n2]);
            }
            // pass 1 (+2 for bf16): Ah*Bh (+ Ah*Bl)
#pragma unroll
            for (int mi = 0; mi < 4; mi++)
#pragma unroll
                for (int ni = 0; ni < 8; ni++) {
                    float* cc = &acc[(mi * 8 + ni) * 4];
                    if (M2 == 0) {
                        mma_bf16(cc, a4[mi], bh4[ni >> 1][ni & 1], bh4[ni >> 1][(ni & 1) + 2]);
                        mma_bf16(cc, a4[mi], bl4[ni >> 1][ni & 1], bl4[ni >> 1][(ni & 1) + 2]);
                    } else {
                        mma_f16(cc, a4[mi], bh4[ni >> 1][ni & 1], bh4[ni >> 1][(ni & 1) + 2]);
                    }
                }
            // last pass: Al*Bh
#pragma unroll
            for (int mi = 0; mi < 4; mi++)
                ldsm4(stAl + swz((uint32_t)((arow + mi * 16) * 128 + cb)), a4[mi]);
#pragma unroll
            for (int mi = 0; mi < 4; mi++)
#pragma unroll
                for (int ni = 0; ni < 8; ni++) {
                    float* cc = &acc[(mi * 8 + ni) * 4];
                    if (M2 == 0)
                        mma_bf16(cc, a4[mi], bh4[ni >> 1][ni & 1], bh4[ni >> 1][(ni & 1) + 2]);
                    else
                        mma_f16(cc, a4[mi], bh4[ni >> 1][ni & 1], bh4[ni >> 1][(ni & 1) + 2]);
                }
        }

        if (kc + 1 < nk) cp_wait0();
        __syncthreads();
    }

    // ---------------- epilogue ----------------
    const int r  = lane >> 2;
    const int c2 = (lane & 3) * 2;
#pragma unroll
    for (int mi = 0; mi < 4; mi++) {
#pragma unroll
        for (int ni = 0; ni < 8; ni++) {
            float* cc = &acc[(mi * 8 + ni) * 4];
            int col = n0 + wn * 64 + ni * 8 + c2;
#pragma unroll
            for (int half = 0; half < 2; half++) {
                int m = m0 + wm * 64 + mi * 16 + r + half * 8;
                float v0 = cc[half * 2], v1 = cc[half * 2 + 1];
                if (bias) { v0 += bias[col]; v1 += bias[col + 1]; }
                if (silu) {
                    v0 = v0 / (1.f + __expf(-v0));
                    v1 = v1 / (1.f + __expf(-v1));
                }
                if (res) {
                    v0 += res[(size_t)m * N + col];
                    v1 += res[(size_t)m * N + col + 1];
                }
                if (Cf) *(float2*)(Cf + (size_t)m * N + col) = make_float2(v0, v1);
                if (Chalf) *(uint32_t*)(Chalf + (size_t)m * N + col) = pk2h(v0, v1);
                if (Ch) {
                    __nv_bfloat16 h0 = __float2bfloat16(v0);
                    __nv_bfloat16 h1 = __float2bfloat16(v1);
                    __nv_bfloat16 l0 = __float2bfloat16(v0 - __bfloat162float(h0));
                    __nv_bfloat16 l1 = __float2bfloat16(v1 - __bfloat162float(h1));
                    *(uint32_t*)(Ch + (size_t)m * N + col) = pk2(h0, h1);
                    *(uint32_t*)(Cl + (size_t)m * N + col) = pk2(l0, l1);
                }
            }
        }
    }
}

// ---------------- HMMA fp16 flash attention ----------------
// grid (S/64, H, B), 128 threads (4 warps). Warp w owns queries w*16..+15.
// Tile-wise online softmax; Q/K/V fp16 in smem (SW128-style swizzle, 128B rows).
__global__ __launch_bounds__(128) void attn_hmma(
    const __half* __restrict__ qkvh,
    __nv_bfloat16* __restrict__ oh, __nv_bfloat16* __restrict__ ol)
{
    __shared__ __align__(128) char smem[24576];  // Q 8KB | K 8KB | V 8KB
    uint32_t sb = smem_u32(smem);
    const uint32_t qs = sb, ks = sb + 8192, vs = sb + 16384;

    const int qt = blockIdx.x;
    const int h  = blockIdx.y;
    const int b  = blockIdx.z;
    const int tid = threadIdx.x;
    const int warp = tid >> 5;
    const int lane = tid & 31;

    // load Q tile (scaled by HD^-0.5)
    for (int idx = tid; idx < 4096; idx += 128) {
        int row = idx >> 6, col = idx & 63;
        const __half* p = qkvh + (size_t)(b * SS + qt * 64 + row) * (3 * DD) + h * 192 + col;
        *(__half*)(smem + swz((uint32_t)(row * 128 + col * 2))) =
            __float2half_rn(__half2float(*p) * 0.125f);
    }
    __syncthreads();

    const int lr8  = lane & 7;
    const int radd = ((lane >> 3) & 1) * 8;
    const int cadd = (lane >> 4) * 16;
    const int arow = warp * 16 + lr8 + radd;

    uint32_t qa[4][4];
#pragma unroll
    for (int kk = 0; kk < 4; kk++)
        ldsm4(qs + swz((uint32_t)(arow * 128 + kk * 32 + cadd)), qa[kk]);

    float o[8][4];
#pragma unroll
    for (int f = 0; f < 8; f++)
#pragma unroll
        for (int j = 0; j < 4; j++) o[f][j] = 0.f;
    float m0v = -1e30f, m1v = -1e30f, l0 = 0.f, l1 = 0.f;
    const int rq0 = qt * 64 + warp * 16 + (lane >> 2);  // global row for c0,c1

    for (int kt = 0; kt <= qt; kt++) {
        __syncthreads();
        for (int idx = tid; idx < 4096; idx += 128) {
            int row = idx >> 6, col = idx & 63;
            const __half* base = qkvh + (size_t)(b * SS + kt * 64 + row) * (3 * DD) + h * 192;
            uint32_t so = swz((uint32_t)(row * 128 + col * 2));
            *(__half*)(smem + 8192 + so)  = base[64 + col];
            *(__half*)(smem + 16384 + so) = base[128 + col];
        }
        __syncthreads();

        // scores: S = Q K^T  (m16 x n64 per warp)
        float s[8][4];
#pragma unroll
        for (int f = 0; f < 8; f++)
#pragma unroll
            for (int j = 0; j < 4; j++) s[f][j] = 0.f;
#pragma unroll
        for (int kk = 0; kk < 4; kk++) {
            int cb = kk * 32 + cadd;
            uint32_t bf[4][4];
#pragma unroll
            for (int n2 = 0; n2 < 4; n2++)
                ldsm4(ks + swz((uint32_t)((n2 * 16 + lr8 + radd) * 128 + cb)), bf[n2]);
#pragma unroll
            for (int ni = 0; ni < 8; ni++)
                mma_f16(s[ni], qa[kk], bf[ni >> 1][ni & 1], bf[ni >> 1][(ni & 1) + 2]);
        }

        // causal mask (diagonal tile only)
        if (kt == qt) {
#pragma unroll
            for (int f = 0; f < 8; f++)
#pragma unroll
                for (int j = 0; j < 4; j++) {
                    int kc = kt * 64 + f * 8 + (lane & 3) * 2 + (j & 1);
                    int rr = rq0 + ((j >= 2) ? 8 : 0);
                    if (kc > rr) s[f][j] = -1e30f;
                }
        }

        // tile softmax
        float tm0 = -1e30f, tm1 = -1e30f;
#pragma unroll
        for (int f = 0; f < 8; f++) {
            tm0 = fmaxf(tm0, fmaxf(s[f][0], s[f][1]));
            tm1 = fmaxf(tm1, fmaxf(s[f][2], s[f][3]));
        }
        tm0 = fmaxf(tm0, __shfl_xor_sync(0xffffffffu, tm0, 1));
        tm0 = fmaxf(tm0, __shfl_xor_sync(0xffffffffu, tm0, 2));
        tm1 = fmaxf(tm1, __shfl_xor_sync(0xffffffffu, tm1, 1));
        tm1 = fmaxf(tm1, __shfl_xor_sync(0xffffffffu, tm1, 2));
        float nm0 = fmaxf(m0v, tm0), nm1 = fmaxf(m1v, tm1);
        float f0 = __expf(m0v - nm0), f1 = __expf(m1v - nm1);
        float ts0 = 0.f, ts1 = 0.f;
#pragma unroll
        for (int f = 0; f < 8; f++) {
            s[f][0] = __expf(s[f][0] - nm0);
            s[f][1] = __expf(s[f][1] - nm0);
            s[f][2] = __expf(s[f][2] - nm1);
            s[f][3] = __expf(s[f][3] - nm1);
            ts0 += s[f][0] + s[f][1];
            ts1 += s[f][2] + s[f][3];
        }
        ts0 += __shfl_xor_sync(0xffffffffu, ts0, 1);
        ts0 += __shfl_xor_sync(0xffffffffu, ts0, 2);
        ts1 += __shfl_xor_sync(0xffffffffu, ts1, 1);
        ts1 += __shfl_xor_sync(0xffffffffu, ts1, 2);
        l0 = l0 * f0 + ts0; l1 = l1 * f1 + ts1;
        m0v = nm0; m1v = nm1;
#pragma unroll
        for (int f = 0; f < 8; f++) {
            o[f][0] *= f0; o[f][1] *= f0; o[f][2] *= f1; o[f][3] *= f1;
        }

        // P -> fp16 A-frags
        uint32_t pa[4][4];
#pragma unroll
        for (int kk = 0; kk < 4; kk++) {
            pa[kk][0] = pk2h(s[2 * kk][0],     s[2 * kk][1]);
            pa[kk][1] = pk2h(s[2 * kk][2],     s[2 * kk][3]);
            pa[kk][2] = pk2h(s[2 * kk + 1][0], s[2 * kk + 1][1]);
            pa[kk][3] = pk2h(s[2 * kk + 1][2], s[2 * kk + 1][3]);
        }
        // O += P V
#pragma unroll
        for (int kk = 0; kk < 4; kk++) {
            uint32_t vbf[4][4];
#pragma unroll
            for (int ng = 0; ng < 4; ng++)
                ldsm4t(vs + swz((uint32_t)((kk * 16 + lr8 + radd) * 128 + ng * 32 + cadd)), vbf[ng]);
#pragma unroll
            for (int ni = 0; ni < 8; ni++)
                mma_f16(o[ni], pa[kk], vbf[ni >> 1][(ni & 1) * 2], vbf[ni >> 1][(ni & 1) * 2 + 1]);
        }
    }

    float il0 = 1.f / l0, il1 = 1.f / l1;
    const int row0 = b * SS + rq0;
#pragma unroll
    for (int f = 0; f < 8; f++) {
        int col = h * 64 + f * 8 + (lane & 3) * 2;
        float v0 = o[f][0] * il0, v1 = o[f][1] * il0;
        float v2 = o[f][2] * il1, v3 = o[f][3] * il1;
        __nv_bfloat16 h0 = __float2bfloat16(v0), h1 = __float2bfloat16(v1);
        __nv_bfloat16 h2 = __float2bfloat16(v2), h3 = __float2bfloat16(v3);
        size_t p0 = (size_t)row0 * DD + col;
        size_t p1 = (size_t)(row0 + 8) * DD + col;
        *(uint32_t*)(oh + p0) = pk2(h0, h1);
        *(uint32_t*)(ol + p0) = pk2(__float2bfloat16(v0 - __bfloat162float(h0)),
                                    __float2bfloat16(v1 - __bfloat162float(h1)));
        *(uint32_t*)(oh + p1) = pk2(h2, h3);
        *(uint32_t*)(ol + p1) = pk2(__float2bfloat16(v2 - __bfloat162float(h2)),
                                    __float2bfloat16(v3 - __bfloat162float(h3)));
    }
}

// ---------------- launch ----------------
extern "C" void kernel_launch(void* const* d_in, const int* in_sizes, int n_in,
                              void* d_out, int out_size)
{
    const int*   idx     = (const int*)d_in[0];
    const float* tok_emb = (const float*)d_in[1];
    const float* pos_emb = (const float*)d_in[2];
    const float* qkv_w   = (const float*)d_in[3];
    const float* proj_w  = (const float*)d_in[4];
    const float* proj_b  = (const float*)d_in[5];
    const float* ln1_g   = (const float*)d_in[6];
    const float* ln1_b   = (const float*)d_in[7];
    const float* ln2_g   = (const float*)d_in[8];
    const float* ln2_b   = (const float*)d_in[9];
    const float* w1      = (const float*)d_in[10];
    const float* b1      = (const float*)d_in[11];
    const float* w2      = (const float*)d_in[12];
    const float* b2      = (const float*)d_in[13];
    const float* lnf_g   = (const float*)d_in[14];
    const float* lnf_b   = (const float*)d_in[15];
    const float* head_w  = (const float*)d_in[16];
    const float* head_b  = (const float*)d_in[17];
    float* out = (float*)d_out;

    float* x;
    __half* qkvh;
    __nv_bfloat16 *lnh, *lnl, *ah, *al, *ffh, *ffl, *wh, *wl;
    cudaGetSymbolAddress((void**)&x, g_x);
    cudaGetSymbolAddress((void**)&qkvh, g_qkvh);
    cudaGetSymbolAddress((void**)&lnh, g_lnh);
    cudaGetSymbolAddress((void**)&lnl, g_lnl);
    cudaGetSymbolAddress((void**)&ah, g_ah);
    cudaGetSymbolAddress((void**)&al, g_al);
    cudaGetSymbolAddress((void**)&ffh, g_ffh);
    cudaGetSymbolAddress((void**)&ffl, g_ffl);
    cudaGetSymbolAddress((void**)&wh, g_wh);
    cudaGetSymbolAddress((void**)&wl, g_wl);

    cudaFuncSetAttribute(gemm_tc<0>, cudaFuncAttributeMaxDynamicSharedMemorySize, SMEM_GEMM);
    cudaFuncSetAttribute(gemm_tc<1>, cudaFuncAttributeMaxDynamicSharedMemorySize, SMEM_GEMM);

    // split weights: layer weights bf16 hi/lo, head single fp16
    split_kernel<<<NQKV / 1024, 256>>>((const float4*)qkv_w, (uint2*)(wh + OFF_QKV), (uint2*)(wl + OFF_QKV), NQKV / 4);
    split_kernel<<<NPROJ / 1024, 256>>>((const float4*)proj_w, (uint2*)(wh + OFF_PROJ), (uint2*)(wl + OFF_PROJ), NPROJ / 4);
    split_kernel<<<NW1 / 1024, 256>>>((const float4*)w1, (uint2*)(wh + OFF_W1), (uint2*)(wl + OFF_W1), NW1 / 4);
    split_kernel<<<NW2 / 1024, 256>>>((const float4*)w2, (uint2*)(wh + OFF_W2), (uint2*)(wl + OFF_W2), NW2 / 4);
    split_half_kernel<<<NHEAD / 1024, 256>>>((const float4*)head_w, (uint2*)(wh + OFF_HEAD), NHEAD / 4);

    embed_kernel<<<NTOK, 256>>>(idx, tok_emb, pos_emb, x);

    for (int l = 0; l < LL; l++) {
        // ln1 -> qkv (fp16 out for attention)
        ln_kernel<0><<<NTOK, 256>>>(x, ln1_g + l * DD, ln1_b + l * DD, lnh, lnl);
        gemm_tc<0><<<dim3(32, 12), 256, SMEM_GEMM>>>(
            lnh, lnl, wh + OFF_QKV + (size_t)l * 3 * DD * DD, wl + OFF_QKV + (size_t)l * 3 * DD * DD,
            nullptr, nullptr, nullptr, qkvh, nullptr, nullptr, NTOK, 3 * DD, DD, 0);
        // attention (HMMA flash) -> split bf16 output
        attn_hmma<<<dim3(SS / 64, HH, BB), 128>>>(qkvh, ah, al);
        // proj + residual (fp32 x)
        gemm_tc<0><<<dim3(32, 4), 256, SMEM_GEMM>>>(
            ah, al, wh + OFF_PROJ + (size_t)l * DD * DD, wl + OFF_PROJ + (size_t)l * DD * DD,
            proj_b + l * DD, x, x, nullptr, nullptr, nullptr, NTOK, DD, DD, 0);
        // ln2 -> MLP
        ln_kernel<0><<<NTOK, 256>>>(x, ln2_g + l * DD, ln2_b + l * DD, lnh, lnl);
        gemm_tc<0><<<dim3(32, 16), 256, SMEM_GEMM>>>(
            lnh, lnl, wh + OFF_W1 + (size_t)l * FF_DIM * DD, wl + OFF_W1 + (size_t)l * FF_DIM * DD,
            b1 + l * FF_DIM, nullptr, nullptr, nullptr, ffh, ffl, NTOK, FF_DIM, DD, 1);
        gemm_tc<0><<<dim3(32, 4), 256, SMEM_GEMM>>>(
            ffh, ffl, wh + OFF_W2 + (size_t)l * DD * FF_DIM, wl + OFF_W2 + (size_t)l * DD * FF_DIM,
            b2 + l * DD, x, x, nullptr, nullptr, nullptr, NTOK, DD, FF_DIM, 0);
    }

    // final LN (fp16 split) + LM head (fp16 2-pass)
    ln_kernel<1><<<NTOK, 256>>>(x, lnf_g, lnf_b, lnh, lnl);
    gemm_tc<1><<<dim3(32, VV / 256), 256, SMEM_GEMM>>>(
        lnh, lnl, wh + OFF_HEAD, nullptr,
        head_b, nullptr, out, nullptr, nullptr, nullptr, NTOK, VV, DD, 0);
}

// round 11
// speedup vs baseline: 4.9177x; 1.2697x over previous
#include <cuda_runtime.h>
#include <cuda_bf16.h>
#include <cuda_fp16.h>
#include <math.h>
#include <stdint.h>

// Model dims
#define BB 4
#define SS 1024
#define VV 32000
#define DD 1024
#define HH 16
#define HD 64
#define LL 8
#define FF_DIM 4096
#define NTOK (BB * SS)   // 4096

// Weight element counts / offsets inside the fp16 weight buffer
#define NQKV   25165824
#define NPROJ  8388608
#define NW1    33554432
#define NW2    33554432
#define NHEAD  32768000
#define OFF_QKV  0
#define OFF_PROJ 25165824
#define OFF_W1   33554432
#define OFF_W2   67108864
#define OFF_HEAD 100663296
#define TOTW     133431296

// stage: Ah 16KB + Al 16KB + B 32KB = 64KB; 2 stages
#define STAGE_BYTES 65536
#define SMEM_GEMM (1024 + 2 * STAGE_BYTES)

// ---------------- scratch (device globals; no allocation) ----------------
__device__ float g_x[NTOK * DD];          // residual stream (fp32)
__device__ __half g_qkvh[NTOK * 3 * DD];  // qkv projection (fp16, attn input)
__device__ __half g_lnh[NTOK * DD], g_lnl[NTOK * DD];
__device__ __half g_ah [NTOK * DD], g_al [NTOK * DD];
__device__ __half g_ffh[NTOK * FF_DIM], g_ffl[NTOK * FF_DIM];
__device__ __half g_w[TOTW];              // all weights, single fp16

// ---------------- PTX helpers (baseline ISA only) ----------------
__device__ __forceinline__ uint32_t smem_u32(const void* p) {
    uint32_t a;
    asm("{ .reg .u64 t; cvta.to.shared.u64 t, %1; cvt.u32.u64 %0, t; }" : "=r"(a) : "l"(p));
    return a;
}
__device__ __forceinline__ void cp16(uint32_t s, const void* g) {
    asm volatile("cp.async.cg.shared.global [%0], [%1], 16;" :: "r"(s), "l"(g) : "memory");
}
__device__ __forceinline__ void cp_commit() { asm volatile("cp.async.commit_group;" ::: "memory"); }
__device__ __forceinline__ void cp_wait0()  { asm volatile("cp.async.wait_group 0;" ::: "memory"); }

__device__ __forceinline__ void ldsm4(uint32_t addr, uint32_t* r) {
    asm volatile("ldmatrix.sync.aligned.m8n8.x4.shared.b16 {%0,%1,%2,%3}, [%4];"
        : "=r"(r[0]), "=r"(r[1]), "=r"(r[2]), "=r"(r[3]) : "r"(addr));
}
__device__ __forceinline__ void ldsm4t(uint32_t addr, uint32_t* r) {
    asm volatile("ldmatrix.sync.aligned.m8n8.x4.trans.shared.b16 {%0,%1,%2,%3}, [%4];"
        : "=r"(r[0]), "=r"(r[1]), "=r"(r[2]), "=r"(r[3]) : "r"(addr));
}
__device__ __forceinline__ void mma_f16(float* c, const uint32_t* a, uint32_t b0, uint32_t b1) {
    asm volatile(
        "mma.sync.aligned.m16n8k16.row.col.f32.f16.f16.f32 "
        "{%0,%1,%2,%3}, {%4,%5,%6,%7}, {%8,%9}, {%0,%1,%2,%3};"
        : "+f"(c[0]), "+f"(c[1]), "+f"(c[2]), "+f"(c[3])
        : "r"(a[0]), "r"(a[1]), "r"(a[2]), "r"(a[3]), "r"(b0), "r"(b1));
}
__device__ __forceinline__ uint32_t swz(uint32_t off) { return off ^ ((off >> 3) & 0x70); }

__device__ __forceinline__ uint32_t pk2h(float a, float b) {
    __half2 h = __floats2half2_rn(a, b);
    return *(uint32_t*)&h;
}

// ---------------- weight round: fp32 -> single fp16 ----------------
__global__ __launch_bounds__(256) void split_half_kernel(
    const float4* __restrict__ w, uint2* __restrict__ h, int n4)
{
    int i = blockIdx.x * 256 + threadIdx.x;
    if (i >= n4) return;
    float4 v = w[i];
    uint2 hv;
    hv.x = pk2h(v.x, v.y); hv.y = pk2h(v.z, v.w);
    h[i] = hv;
}

// ---------------- embedding ----------------
__global__ __launch_bounds__(256) void embed_kernel(
    const int* __restrict__ idx, const float* __restrict__ tok,
    const float* __restrict__ pos, float* __restrict__ x)
{
    int t = blockIdx.x;
    int s = t & (SS - 1);
    int token = idx[t];
    const float* te = tok + (size_t)token * DD;
    const float* pe = pos + (size_t)s * DD;
    float* xr = x + (size_t)t * DD;
    for (int d = threadIdx.x; d < DD; d += 256) xr[d] = te[d] + pe[d];
}

// ---------------- layernorm -> split fp16 hi/lo ----------------
__global__ __launch_bounds__(256) void ln_kernel(
    const float* __restrict__ x, const float* __restrict__ gw,
    const float* __restrict__ bw, __half* __restrict__ yh,
    __half* __restrict__ yl)
{
    __shared__ float rs[8], rq[8];
    int row = blockIdx.x;
    const float* xr = x + (size_t)row * DD;
    float v[4];
    float sum = 0.f, sq = 0.f;
#pragma unroll
    for (int i = 0; i < 4; i++) {
        v[i] = xr[threadIdx.x + i * 256];
        sum += v[i];
        sq += v[i] * v[i];
    }
#pragma unroll
    for (int o = 16; o; o >>= 1) {
        sum += __shfl_xor_sync(0xffffffffu, sum, o);
        sq  += __shfl_xor_sync(0xffffffffu, sq, o);
    }
    int warp = threadIdx.x >> 5;
    if ((threadIdx.x & 31) == 0) { rs[warp] = sum; rq[warp] = sq; }
    __syncthreads();
    float ts = 0.f, tq = 0.f;
#pragma unroll
    for (int w = 0; w < 8; w++) { ts += rs[w]; tq += rq[w]; }
    float mu = ts * (1.f / DD);
    float var = tq * (1.f / DD) - mu * mu;
    float inv = rsqrtf(var + 1e-5f);
#pragma unroll
    for (int i = 0; i < 4; i++) {
        int d = threadIdx.x + i * 256;
        float y = (v[i] - mu) * inv * gw[d] + bw[d];
        __half h = __float2half_rn(y);
        yh[(size_t)row * DD + d] = h;
        yl[(size_t)row * DD + d] = __float2half_rn(y - __half2float(h));
    }
}

// ---------------- fp16 2-pass mma.sync GEMM ----------------
// C[M,N] = (Ah+Al)[M,K] @ B[N,K]^T   (A fp16 hi/lo, B single fp16)
// CTA tile 128x256, BK=64, 8 warps (2m x 4n), warp tile 64x64.
__global__ __launch_bounds__(256, 1) void gemm_tc(
    const __half* __restrict__ Ah, const __half* __restrict__ Al,
    const __half* __restrict__ B,
    const float* __restrict__ bias, const float* __restrict__ res,
    float* __restrict__ Cf, __half* __restrict__ Cs,
    __half* __restrict__ Chh, __half* __restrict__ Cll,
    int M, int N, int K, int silu)
{
    extern __shared__ char smem[];
    const int tid = threadIdx.x;
    const int wid = tid >> 5;
    const int lane = tid & 31;
    const int m0 = blockIdx.x * 128;
    const int n0 = blockIdx.y * 256;
    const int wm = wid & 1;
    const int wn = wid >> 1;

    uint32_t sbase = smem_u32(smem);
    uint32_t tiles = (sbase + 1023) & ~1023u;
    // stage: Ah @0 (16KB), Al @16K (16KB), B @32K (32KB)

    uint32_t swoA[4];
    const char *gA[4], *gAl[4];
    uint32_t swoB[8];
    const char *gB[8];
#pragma unroll
    for (int u = 0; u < 4; u++) {
        int unit = tid + u * 256;
        int row = unit >> 3;
        int cb = (unit & 7) * 16;
        swoA[u] = swz((uint32_t)(row * 128 + cb));
        gA[u]  = (const char*)Ah + ((size_t)(m0 + row) * K) * 2 + cb;
        gAl[u] = (const char*)Al + ((size_t)(m0 + row) * K) * 2 + cb;
    }
#pragma unroll
    for (int u = 0; u < 8; u++) {
        int unit = tid + u * 256;
        int row = unit >> 3;
        int cb = (unit & 7) * 16;
        swoB[u] = swz((uint32_t)(row * 128 + cb));
        gB[u] = (const char*)B + ((size_t)(n0 + row) * K) * 2 + cb;
    }

    const int lr8  = lane & 7;
    const int radd = ((lane >> 3) & 1) * 8;
    const int cadd = (lane >> 4) * 16;
    const int arow = wm * 64 + lr8 + radd;
    const int brow = wn * 64 + lr8 + radd;

    float acc[128];
#pragma unroll
    for (int i = 0; i < 128; i++) acc[i] = 0.f;

    const int nk = K >> 6;

    {
        uint32_t st = tiles;
#pragma unroll
        for (int u = 0; u < 4; u++) {
            cp16(st + swoA[u],         gA[u]);
            cp16(st + 16384 + swoA[u], gAl[u]);
        }
#pragma unroll
        for (int u = 0; u < 8; u++)
            cp16(st + 32768 + swoB[u], gB[u]);
        cp_commit(); cp_wait0();
    }
    __syncthreads();

    for (int kc = 0; kc < nk; kc++) {
        int b = kc & 1;
        uint32_t st = tiles + (uint32_t)b * STAGE_BYTES;

        if (kc + 1 < nk) {
            uint32_t st2 = tiles + (uint32_t)(b ^ 1) * STAGE_BYTES;
            size_t koff = (size_t)(kc + 1) * 128;
#pragma unroll
            for (int u = 0; u < 4; u++) {
                cp16(st2 + swoA[u],         gA[u] + koff);
                cp16(st2 + 16384 + swoA[u], gAl[u] + koff);
            }
#pragma unroll
            for (int u = 0; u < 8; u++)
                cp16(st2 + 32768 + swoB[u], gB[u] + koff);
            cp_commit();
        }

        uint32_t stA = st, stAl = st + 16384, stB = st + 32768;
#pragma unroll
        for (int ks = 0; ks < 4; ks++) {
            int cb = ks * 32 + cadd;
            uint32_t a4[4][4], b4[4][4];
#pragma unroll
            for (int mi = 0; mi < 4; mi++)
                ldsm4(stA + swz((uint32_t)((arow + mi * 16) * 128 + cb)), a4[mi]);
#pragma unroll
            for (int n2 = 0; n2 < 4; n2++)
                ldsm4(stB + swz((uint32_t)((brow + n2 * 16) * 128 + cb)), b4[n2]);
            // pass 1: Ah*B
#pragma unroll
            for (int mi = 0; mi < 4; mi++)
#pragma unroll
                for (int ni = 0; ni < 8; ni++)
                    mma_f16(&acc[(mi * 8 + ni) * 4], a4[mi],
                            b4[ni >> 1][ni & 1], b4[ni >> 1][(ni & 1) + 2]);
            // pass 2: Al*B
#pragma unroll
            for (int mi = 0; mi < 4; mi++)
                ldsm4(stAl + swz((uint32_t)((arow + mi * 16) * 128 + cb)), a4[mi]);
#pragma unroll
            for (int mi = 0; mi < 4; mi++)
#pragma unroll
                for (int ni = 0; ni < 8; ni++)
                    mma_f16(&acc[(mi * 8 + ni) * 4], a4[mi],
                            b4[ni >> 1][ni & 1], b4[ni >> 1][(ni & 1) + 2]);
        }

        if (kc + 1 < nk) cp_wait0();
        __syncthreads();
    }

    // ---------------- epilogue ----------------
    const int r  = lane >> 2;
    const int c2 = (lane & 3) * 2;
#pragma unroll
    for (int mi = 0; mi < 4; mi++) {
#pragma unroll
        for (int ni = 0; ni < 8; ni++) {
            float* cc = &acc[(mi * 8 + ni) * 4];
            int col = n0 + wn * 64 + ni * 8 + c2;
#pragma unroll
            for (int half = 0; half < 2; half++) {
                int m = m0 + wm * 64 + mi * 16 + r + half * 8;
                float v0 = cc[half * 2], v1 = cc[half * 2 + 1];
                if (bias) { v0 += bias[col]; v1 += bias[col + 1]; }
                if (silu) {
                    v0 = v0 / (1.f + __expf(-v0));
                    v1 = v1 / (1.f + __expf(-v1));
                }
                if (res) {
                    v0 += res[(size_t)m * N + col];
                    v1 += res[(size_t)m * N + col + 1];
                }
                if (Cf) *(float2*)(Cf + (size_t)m * N + col) = make_float2(v0, v1);
                if (Cs) *(uint32_t*)(Cs + (size_t)m * N + col) = pk2h(v0, v1);
                if (Chh) {
                    __half h0 = __float2half_rn(v0);
                    __half h1 = __float2half_rn(v1);
                    *(uint32_t*)(Chh + (size_t)m * N + col) =
                        (uint32_t)__half_as_ushort(h0) | ((uint32_t)__half_as_ushort(h1) << 16);
                    *(uint32_t*)(Cll + (size_t)m * N + col) =
                        pk2h(v0 - __half2float(h0), v1 - __half2float(h1));
                }
            }
        }
    }
}

// ---------------- HMMA fp16 flash attention ----------------
// grid (S/64, H, B), 128 threads (4 warps). Warp w owns queries w*16..+15.
__global__ __launch_bounds__(128) void attn_hmma(
    const __half* __restrict__ qkvh,
    __half* __restrict__ oh, __half* __restrict__ ol)
{
    __shared__ __align__(128) char smem[24576];  // Q 8KB | K 8KB | V 8KB
    uint32_t sb = smem_u32(smem);
    const uint32_t qs = sb, ks = sb + 8192, vs = sb + 16384;

    const int qt = blockIdx.x;
    const int h  = blockIdx.y;
    const int b  = blockIdx.z;
    const int tid = threadIdx.x;
    const int warp = tid >> 5;
    const int lane = tid & 31;

    // load Q tile (scaled by HD^-0.5)
    for (int idx = tid; idx < 4096; idx += 128) {
        int row = idx >> 6, col = idx & 63;
        const __half* p = qkvh + (size_t)(b * SS + qt * 64 + row) * (3 * DD) + h * 192 + col;
        *(__half*)(smem + swz((uint32_t)(row * 128 + col * 2))) =
            __float2half_rn(__half2float(*p) * 0.125f);
    }
    __syncthreads();

    const int lr8  = lane & 7;
    const int radd = ((lane >> 3) & 1) * 8;
    const int cadd = (lane >> 4) * 16;
    const int arow = warp * 16 + lr8 + radd;

    uint32_t qa[4][4];
#pragma unroll
    for (int kk = 0; kk < 4; kk++)
        ldsm4(qs + swz((uint32_t)(arow * 128 + kk * 32 + cadd)), qa[kk]);

    float o[8][4];
#pragma unroll
    for (int f = 0; f < 8; f++)
#pragma unroll
        for (int j = 0; j < 4; j++) o[f][j] = 0.f;
    float m0v = -1e30f, m1v = -1e30f, l0 = 0.f, l1 = 0.f;
    const int rq0 = qt * 64 + warp * 16 + (lane >> 2);

    for (int kt = 0; kt <= qt; kt++) {
        __syncthreads();
        for (int idx = tid; idx < 4096; idx += 128) {
            int row = idx >> 6, col = idx & 63;
            const __half* base = qkvh + (size_t)(b * SS + kt * 64 + row) * (3 * DD) + h * 192;
            uint32_t so = swz((uint32_t)(row * 128 + col * 2));
            *(__half*)(smem + 8192 + so)  = base[64 + col];
            *(__half*)(smem + 16384 + so) = base[128 + col];
        }
        __syncthreads();

        float s[8][4];
#pragma unroll
        for (int f = 0; f < 8; f++)
#pragma unroll
            for (int j = 0; j < 4; j++) s[f][j] = 0.f;
#pragma unroll
        for (int kk = 0; kk < 4; kk++) {
            int cb = kk * 32 + cadd;
            uint32_t bf[4][4];
#pragma unroll
            for (int n2 = 0; n2 < 4; n2++)
                ldsm4(ks + swz((uint32_t)((n2 * 16 + lr8 + radd) * 128 + cb)), bf[n2]);
#pragma unroll
            for (int ni = 0; ni < 8; ni++)
                mma_f16(s[ni], qa[kk], bf[ni >> 1][ni & 1], bf[ni >> 1][(ni & 1) + 2]);
        }

        if (kt == qt) {
#pragma unroll
            for (int f = 0; f < 8; f++)
#pragma unroll
                for (int j = 0; j < 4; j++) {
                    int kc = kt * 64 + f * 8 + (lane & 3) * 2 + (j & 1);
                    int rr = rq0 + ((j >= 2) ? 8 : 0);
                    if (kc > rr) s[f][j] = -1e30f;
                }
        }

        float tm0 = -1e30f, tm1 = -1e30f;
#pragma unroll
        for (int f = 0; f < 8; f++) {
            tm0 = fmaxf(tm0, fmaxf(s[f][0], s[f][1]));
            tm1 = fmaxf(tm1, fmaxf(s[f][2], s[f][3]));
        }
        tm0 = fmaxf(tm0, __shfl_xor_sync(0xffffffffu, tm0, 1));
        tm0 = fmaxf(tm0, __shfl_xor_sync(0xffffffffu, tm0, 2));
        tm1 = fmaxf(tm1, __shfl_xor_sync(0xffffffffu, tm1, 1));
        tm1 = fmaxf(tm1, __shfl_xor_sync(0xffffffffu, tm1, 2));
        float nm0 = fmaxf(m0v, tm0), nm1 = fmaxf(m1v, tm1);
        float f0 = __expf(m0v - nm0), f1 = __expf(m1v - nm1);
        float ts0 = 0.f, ts1 = 0.f;
#pragma unroll
        for (int f = 0; f < 8; f++) {
            s[f][0] = __expf(s[f][0] - nm0);
            s[f][1] = __expf(s[f][1] - nm0);
            s[f][2] = __expf(s[f][2] - nm1);
            s[f][3] = __expf(s[f][3] - nm1);
            ts0 += s[f][0] + s[f][1];
            ts1 += s[f][2] + s[f][3];
        }
        ts0 += __shfl_xor_sync(0xffffffffu, ts0, 1);
        ts0 += __shfl_xor_sync(0xffffffffu, ts0, 2);
        ts1 += __shfl_xor_sync(0xffffffffu, ts1, 1);
        ts1 += __shfl_xor_sync(0xffffffffu, ts1, 2);
        l0 = l0 * f0 + ts0; l1 = l1 * f1 + ts1;
        m0v = nm0; m1v = nm1;
#pragma unroll
        for (int f = 0; f < 8; f++) {
            o[f][0] *= f0; o[f][1] *= f0; o[f][2] *= f1; o[f][3] *= f1;
        }

        uint32_t pa[4][4];
#pragma unroll
        for (int kk = 0; kk < 4; kk++) {
            pa[kk][0] = pk2h(s[2 * kk][0],     s[2 * kk][1]);
            pa[kk][1] = pk2h(s[2 * kk][2],     s[2 * kk][3]);
            pa[kk][2] = pk2h(s[2 * kk + 1][0], s[2 * kk + 1][1]);
            pa[kk][3] = pk2h(s[2 * kk + 1][2], s[2 * kk + 1][3]);
        }
#pragma unroll
        for (int kk = 0; kk < 4; kk++) {
            uint32_t vbf[4][4];
#pragma unroll
            for (int ng = 0; ng < 4; ng++)
                ldsm4t(vs + swz((uint32_t)((kk * 16 + lr8 + radd) * 128 + ng * 32 + cadd)), vbf[ng]);
#pragma unroll
            for (int ni = 0; ni < 8; ni++)
                mma_f16(o[ni], pa[kk], vbf[ni >> 1][(ni & 1) * 2], vbf[ni >> 1][(ni & 1) * 2 + 1]);
        }
    }

    float il0 = 1.f / l0, il1 = 1.f / l1;
    const int row0 = b * SS + rq0;
#pragma unroll
    for (int f = 0; f < 8; f++) {
        int col = h * 64 + f * 8 + (lane & 3) * 2;
        float v0 = o[f][0] * il0, v1 = o[f][1] * il0;
        float v2 = o[f][2] * il1, v3 = o[f][3] * il1;
        __half h0 = __float2half_rn(v0), h1 = __float2half_rn(v1);
        __half h2 = __float2half_rn(v2), h3 = __float2half_rn(v3);
        size_t p0 = (size_t)row0 * DD + col;
        size_t p1 = (size_t)(row0 + 8) * DD + col;
        *(uint32_t*)(oh + p0) = (uint32_t)__half_as_ushort(h0) | ((uint32_t)__half_as_ushort(h1) << 16);
        *(uint32_t*)(ol + p0) = pk2h(v0 - __half2float(h0), v1 - __half2float(h1));
        *(uint32_t*)(oh + p1) = (uint32_t)__half_as_ushort(h2) | ((uint32_t)__half_as_ushort(h3) << 16);
        *(uint32_t*)(ol + p1) = pk2h(v2 - __half2float(h2), v3 - __half2float(h3));
    }
}

// ---------------- launch ----------------
extern "C" void kernel_launch(void* const* d_in, const int* in_sizes, int n_in,
                              void* d_out, int out_size)
{
    const int*   idx     = (const int*)d_in[0];
    const float* tok_emb = (const float*)d_in[1];
    const float* pos_emb = (const float*)d_in[2];
    const float* qkv_w   = (const float*)d_in[3];
    const float* proj_w  = (const float*)d_in[4];
    const float* proj_b  = (const float*)d_in[5];
    const float* ln1_g   = (const float*)d_in[6];
    const float* ln1_b   = (const float*)d_in[7];
    const float* ln2_g   = (const float*)d_in[8];
    const float* ln2_b   = (const float*)d_in[9];
    const float* w1      = (const float*)d_in[10];
    const float* b1      = (const float*)d_in[11];
    const float* w2      = (const float*)d_in[12];
    const float* b2      = (const float*)d_in[13];
    const float* lnf_g   = (const float*)d_in[14];
    const float* lnf_b   = (const float*)d_in[15];
    const float* head_w  = (const float*)d_in[16];
    const float* head_b  = (const float*)d_in[17];
    float* out = (float*)d_out;

    float* x;
    __half *qkvh, *lnh, *lnl, *ah, *al, *ffh, *ffl, *w;
    cudaGetSymbolAddress((void**)&x, g_x);
    cudaGetSymbolAddress((void**)&qkvh, g_qkvh);
    cudaGetSymbolAddress((void**)&lnh, g_lnh);
    cudaGetSymbolAddress((void**)&lnl, g_lnl);
    cudaGetSymbolAddress((void**)&ah, g_ah);
    cudaGetSymbolAddress((void**)&al, g_al);
    cudaGetSymbolAddress((void**)&ffh, g_ffh);
    cudaGetSymbolAddress((void**)&ffl, g_ffl);
    cudaGetSymbolAddress((void**)&w, g_w);

    cudaFuncSetAttribute(gemm_tc, cudaFuncAttributeMaxDynamicSharedMemorySize, SMEM_GEMM);

    // round all weights to single fp16
    split_half_kernel<<<NQKV / 1024, 256>>>((const float4*)qkv_w, (uint2*)(w + OFF_QKV), NQKV / 4);
    split_half_kernel<<<NPROJ / 1024, 256>>>((const float4*)proj_w, (uint2*)(w + OFF_PROJ), NPROJ / 4);
    split_half_kernel<<<NW1 / 1024, 256>>>((const float4*)w1, (uint2*)(w + OFF_W1), NW1 / 4);
    split_half_kernel<<<NW2 / 1024, 256>>>((const float4*)w2, (uint2*)(w + OFF_W2), NW2 / 4);
    split_half_kernel<<<NHEAD / 1024, 256>>>((const float4*)head_w, (uint2*)(w + OFF_HEAD), NHEAD / 4);

    embed_kernel<<<NTOK, 256>>>(idx, tok_emb, pos_emb, x);

    for (int l = 0; l < LL; l++) {
        // ln1 -> qkv (fp16 out for attention)
        ln_kernel<<<NTOK, 256>>>(x, ln1_g + l * DD, ln1_b + l * DD, lnh, lnl);
        gemm_tc<<<dim3(32, 12), 256, SMEM_GEMM>>>(
            lnh, lnl, w + OFF_QKV + (size_t)l * 3 * DD * DD,
            nullptr, nullptr, nullptr, qkvh, nullptr, nullptr, NTOK, 3 * DD, DD, 0);
        // attention (HMMA flash) -> split fp16 output
        attn_hmma<<<dim3(SS / 64, HH, BB), 128>>>(qkvh, ah, al);
        // proj + residual (fp32 x)
        gemm_tc<<<dim3(32, 4), 256, SMEM_GEMM>>>(
            ah, al, w + OFF_PROJ + (size_t)l * DD * DD,
            proj_b + l * DD, x, x, nullptr, nullptr, nullptr, NTOK, DD, DD, 0);
        // ln2 -> MLP
        ln_kernel<<<NTOK, 256>>>(x, ln2_g + l * DD, ln2_b + l * DD, lnh, lnl);
        gemm_tc<<<dim3(32, 16), 256, SMEM_GEMM>>>(
            lnh, lnl, w + OFF_W1 + (size_t)l * FF_DIM * DD,
            b1 + l * FF_DIM, nullptr, nullptr, nullptr, ffh, ffl, NTOK, FF_DIM, DD, 1);
        gemm_tc<<<dim3(32, 4), 256, SMEM_GEMM>>>(
            ffh, ffl, w + OFF_W2 + (size_t)l * DD * FF_DIM,
            b2 + l * DD, x, x, nullptr, nullptr, nullptr, NTOK, DD, FF_DIM, 0);
    }

    // final LN + LM head
    ln_kernel<<<NTOK, 256>>>(x, lnf_g, lnf_b, lnh, lnl);
    gemm_tc<<<dim3(32, VV / 256), 256, SMEM_GEMM>>>(
        lnh, lnl, w + OFF_HEAD,
        head_b, nullptr, out, nullptr, nullptr, nullptr, NTOK, VV, DD, 0);
}

// round 12
// speedup vs baseline: 5.7363x; 1.1665x over previous
#include <cuda_runtime.h>
#include <cuda_bf16.h>
#include <cuda_fp16.h>
#include <math.h>
#include <stdint.h>

// Model dims
#define BB 4
#define SS 1024
#define VV 32000
#define DD 1024
#define HH 16
#define HD 64
#define LL 8
#define FF_DIM 4096
#define NTOK (BB * SS)   // 4096

// Weight element counts / offsets inside the fp16 weight buffer
#define NQKV   25165824
#define NPROJ  8388608
#define NW1    33554432
#define NW2    33554432
#define NHEAD  32768000
#define OFF_QKV  0
#define OFF_PROJ 25165824
#define OFF_W1   33554432
#define OFF_W2   67108864
#define OFF_HEAD 100663296
#define TOTW     133431296

// stage: Ah 16KB + Al 16KB + B 16KB = 48KB; 2 stages = 96KB (2 CTAs/SM)
#define STAGE_BYTES 49152
#define SMEM_GEMM (1024 + 2 * STAGE_BYTES)

// ---------------- scratch (device globals; no allocation) ----------------
__device__ float g_x[NTOK * DD];          // residual stream (fp32)
__device__ __half g_qkvh[NTOK * 3 * DD];  // qkv projection (fp16, attn input)
__device__ __half g_lnh[NTOK * DD], g_lnl[NTOK * DD];
__device__ __half g_ah [NTOK * DD], g_al [NTOK * DD];
__device__ __half g_ffh[NTOK * FF_DIM], g_ffl[NTOK * FF_DIM];
__device__ __half g_w[TOTW];              // all weights, single fp16

// ---------------- PTX helpers (baseline ISA only) ----------------
__device__ __forceinline__ uint32_t smem_u32(const void* p) {
    uint32_t a;
    asm("{ .reg .u64 t; cvta.to.shared.u64 t, %1; cvt.u32.u64 %0, t; }" : "=r"(a) : "l"(p));
    return a;
}
__device__ __forceinline__ void cp16(uint32_t s, const void* g) {
    asm volatile("cp.async.cg.shared.global [%0], [%1], 16;" :: "r"(s), "l"(g) : "memory");
}
__device__ __forceinline__ void cp_commit() { asm volatile("cp.async.commit_group;" ::: "memory"); }
__device__ __forceinline__ void cp_wait0()  { asm volatile("cp.async.wait_group 0;" ::: "memory"); }

__device__ __forceinline__ void ldsm4(uint32_t addr, uint32_t* r) {
    asm volatile("ldmatrix.sync.aligned.m8n8.x4.shared.b16 {%0,%1,%2,%3}, [%4];"
        : "=r"(r[0]), "=r"(r[1]), "=r"(r[2]), "=r"(r[3]) : "r"(addr));
}
__device__ __forceinline__ void ldsm4t(uint32_t addr, uint32_t* r) {
    asm volatile("ldmatrix.sync.aligned.m8n8.x4.trans.shared.b16 {%0,%1,%2,%3}, [%4];"
        : "=r"(r[0]), "=r"(r[1]), "=r"(r[2]), "=r"(r[3]) : "r"(addr));
}
__device__ __forceinline__ void mma_f16(float* c, const uint32_t* a, uint32_t b0, uint32_t b1) {
    asm volatile(
        "mma.sync.aligned.m16n8k16.row.col.f32.f16.f16.f32 "
        "{%0,%1,%2,%3}, {%4,%5,%6,%7}, {%8,%9}, {%0,%1,%2,%3};"
        : "+f"(c[0]), "+f"(c[1]), "+f"(c[2]), "+f"(c[3])
        : "r"(a[0]), "r"(a[1]), "r"(a[2]), "r"(a[3]), "r"(b0), "r"(b1));
}
__device__ __forceinline__ uint32_t swz(uint32_t off) { return off ^ ((off >> 3) & 0x70); }

__device__ __forceinline__ uint32_t pk2h(float a, float b) {
    __half2 h = __floats2half2_rn(a, b);
    return *(uint32_t*)&h;
}

// ---------------- weight round: fp32 -> single fp16 ----------------
__global__ __launch_bounds__(256) void split_half_kernel(
    const float4* __restrict__ w, uint2* __restrict__ h, int n4)
{
    int i = blockIdx.x * 256 + threadIdx.x;
    if (i >= n4) return;
    float4 v = w[i];
    uint2 hv;
    hv.x = pk2h(v.x, v.y); hv.y = pk2h(v.z, v.w);
    h[i] = hv;
}

// ---------------- embedding ----------------
__global__ __launch_bounds__(256) void embed_kernel(
    const int* __restrict__ idx, const float* __restrict__ tok,
    const float* __restrict__ pos, float* __restrict__ x)
{
    int t = blockIdx.x;
    int s = t & (SS - 1);
    int token = idx[t];
    const float4* te = (const float4*)(tok + (size_t)token * DD);
    const float4* pe = (const float4*)(pos + (size_t)s * DD);
    float4* xr = (float4*)(x + (size_t)t * DD);
    int d = threadIdx.x;
    float4 a = te[d], b = pe[d];
    xr[d] = make_float4(a.x + b.x, a.y + b.y, a.z + b.z, a.w + b.w);
}

// ---------------- layernorm -> split fp16 hi/lo ----------------
__global__ __launch_bounds__(256) void ln_kernel(
    const float* __restrict__ x, const float* __restrict__ gw,
    const float* __restrict__ bw, __half* __restrict__ yh,
    __half* __restrict__ yl)
{
    __shared__ float rs[8], rq[8];
    int row = blockIdx.x;
    const float4* xr = (const float4*)(x + (size_t)row * DD);
    float4 v = xr[threadIdx.x];
    float sum = v.x + v.y + v.z + v.w;
    float sq = v.x * v.x + v.y * v.y + v.z * v.z + v.w * v.w;
#pragma unroll
    for (int o = 16; o; o >>= 1) {
        sum += __shfl_xor_sync(0xffffffffu, sum, o);
        sq  += __shfl_xor_sync(0xffffffffu, sq, o);
    }
    int warp = threadIdx.x >> 5;
    if ((threadIdx.x & 31) == 0) { rs[warp] = sum; rq[warp] = sq; }
    __syncthreads();
    float ts = 0.f, tq = 0.f;
#pragma unroll
    for (int w = 0; w < 8; w++) { ts += rs[w]; tq += rq[w]; }
    float mu = ts * (1.f / DD);
    float var = tq * (1.f / DD) - mu * mu;
    float inv = rsqrtf(var + 1e-5f);
    float4 g = ((const float4*)gw)[threadIdx.x];
    float4 bb = ((const float4*)bw)[threadIdx.x];
    float y0 = (v.x - mu) * inv * g.x + bb.x;
    float y1 = (v.y - mu) * inv * g.y + bb.y;
    float y2 = (v.z - mu) * inv * g.z + bb.z;
    float y3 = (v.w - mu) * inv * g.w + bb.w;
    __half h0 = __float2half_rn(y0), h1 = __float2half_rn(y1);
    __half h2 = __float2half_rn(y2), h3 = __float2half_rn(y3);
    uint2 hv, lv;
    hv.x = (uint32_t)__half_as_ushort(h0) | ((uint32_t)__half_as_ushort(h1) << 16);
    hv.y = (uint32_t)__half_as_ushort(h2) | ((uint32_t)__half_as_ushort(h3) << 16);
    lv.x = pk2h(y0 - __half2float(h0), y1 - __half2float(h1));
    lv.y = pk2h(y2 - __half2float(h2), y3 - __half2float(h3));
    ((uint2*)(yh + (size_t)row * DD))[threadIdx.x] = hv;
    ((uint2*)(yl + (size_t)row * DD))[threadIdx.x] = lv;
}

// ---------------- fp16 2-pass mma.sync GEMM ----------------
// C[M,N] = (Ah+Al)[M,K] @ B[N,K]^T   (A fp16 hi/lo, B single fp16)
// CTA tile 128x128, BK=64, 8 warps (2m x 4n), warp tile 64x32, 2 CTAs/SM.
__global__ __launch_bounds__(256, 2) void gemm_tc(
    const __half* __restrict__ Ah, const __half* __restrict__ Al,
    const __half* __restrict__ B,
    const float* __restrict__ bias, const float* __restrict__ res,
    float* __restrict__ Cf, __half* __restrict__ Cs,
    __half* __restrict__ Chh, __half* __restrict__ Cll,
    int M, int N, int K, int silu)
{
    extern __shared__ char smem[];
    const int tid = threadIdx.x;
    const int wid = tid >> 5;
    const int lane = tid & 31;
    const int m0 = blockIdx.x * 128;
    const int n0 = blockIdx.y * 128;
    const int wm = wid & 1;
    const int wn = wid >> 1;

    uint32_t sbase = smem_u32(smem);
    uint32_t tiles = (sbase + 1023) & ~1023u;
    // stage: Ah @0 (16KB), Al @16K (16KB), B @32K (16KB)

    uint32_t swo[4];
    const char *gA[4], *gAl[4], *gB[4];
#pragma unroll
    for (int u = 0; u < 4; u++) {
        int unit = tid + u * 256;
        int row = unit >> 3;
        int cb = (unit & 7) * 16;
        swo[u] = swz((uint32_t)(row * 128 + cb));
        gA[u]  = (const char*)Ah + ((size_t)(m0 + row) * K) * 2 + cb;
        gAl[u] = (const char*)Al + ((size_t)(m0 + row) * K) * 2 + cb;
        gB[u]  = (const char*)B + ((size_t)(n0 + row) * K) * 2 + cb;
    }

    const int lr8  = lane & 7;
    const int radd = ((lane >> 3) & 1) * 8;
    const int cadd = (lane >> 4) * 16;
    const int arow = wm * 64 + lr8 + radd;
    const int brow = wn * 32 + lr8 + radd;

    float acc[64];
#pragma unroll
    for (int i = 0; i < 64; i++) acc[i] = 0.f;

    const int nk = K >> 6;

    {
        uint32_t st = tiles;
#pragma unroll
        for (int u = 0; u < 4; u++) {
            cp16(st + swo[u],         gA[u]);
            cp16(st + 16384 + swo[u], gAl[u]);
            cp16(st + 32768 + swo[u], gB[u]);
        }
        cp_commit(); cp_wait0();
    }
    __syncthreads();

    for (int kc = 0; kc < nk; kc++) {
        int b = kc & 1;
        uint32_t st = tiles + (uint32_t)b * STAGE_BYTES;

        if (kc + 1 < nk) {
            uint32_t st2 = tiles + (uint32_t)(b ^ 1) * STAGE_BYTES;
            size_t koff = (size_t)(kc + 1) * 128;
#pragma unroll
            for (int u = 0; u < 4; u++) {
                cp16(st2 + swo[u],         gA[u] + koff);
                cp16(st2 + 16384 + swo[u], gAl[u] + koff);
                cp16(st2 + 32768 + swo[u], gB[u] + koff);
            }
            cp_commit();
        }

        uint32_t stA = st, stAl = st + 16384, stB = st + 32768;
#pragma unroll
        for (int ks = 0; ks < 4; ks++) {
            int cb = ks * 32 + cadd;
            uint32_t a4[4][4], b4[2][4];
#pragma unroll
            for (int mi = 0; mi < 4; mi++)
                ldsm4(stA + swz((uint32_t)((arow + mi * 16) * 128 + cb)), a4[mi]);
#pragma unroll
            for (int n2 = 0; n2 < 2; n2++)
                ldsm4(stB + swz((uint32_t)((brow + n2 * 16) * 128 + cb)), b4[n2]);
            // pass 1: Ah*B
#pragma unroll
            for (int mi = 0; mi < 4; mi++)
#pragma unroll
                for (int ni = 0; ni < 4; ni++)
                    mma_f16(&acc[(mi * 4 + ni) * 4], a4[mi],
                            b4[ni >> 1][ni & 1], b4[ni >> 1][(ni & 1) + 2]);
            // pass 2: Al*B
#pragma unroll
            for (int mi = 0; mi < 4; mi++)
                ldsm4(stAl + swz((uint32_t)((arow + mi * 16) * 128 + cb)), a4[mi]);
#pragma unroll
            for (int mi = 0; mi < 4; mi++)
#pragma unroll
                for (int ni = 0; ni < 4; ni++)
                    mma_f16(&acc[(mi * 4 + ni) * 4], a4[mi],
                            b4[ni >> 1][ni & 1], b4[ni >> 1][(ni & 1) + 2]);
        }

        if (kc + 1 < nk) cp_wait0();
        __syncthreads();
    }

    // ---------------- epilogue ----------------
    const int r  = lane >> 2;
    const int c2 = (lane & 3) * 2;
#pragma unroll
    for (int mi = 0; mi < 4; mi++) {
#pragma unroll
        for (int ni = 0; ni < 4; ni++) {
            float* cc = &acc[(mi * 4 + ni) * 4];
            int col = n0 + wn * 32 + ni * 8 + c2;
#pragma unroll
            for (int half = 0; half < 2; half++) {
                int m = m0 + wm * 64 + mi * 16 + r + half * 8;
                float v0 = cc[half * 2], v1 = cc[half * 2 + 1];
                if (bias) { v0 += bias[col]; v1 += bias[col + 1]; }
                if (silu) {
                    v0 = v0 / (1.f + __expf(-v0));
                    v1 = v1 / (1.f + __expf(-v1));
                }
                if (res) {
                    v0 += res[(size_t)m * N + col];
                    v1 += res[(size_t)m * N + col + 1];
                }
                if (Cf) *(float2*)(Cf + (size_t)m * N + col) = make_float2(v0, v1);
                if (Cs) *(uint32_t*)(Cs + (size_t)m * N + col) = pk2h(v0, v1);
                if (Chh) {
                    __half h0 = __float2half_rn(v0);
                    __half h1 = __float2half_rn(v1);
                    *(uint32_t*)(Chh + (size_t)m * N + col) =
                        (uint32_t)__half_as_ushort(h0) | ((uint32_t)__half_as_ushort(h1) << 16);
                    *(uint32_t*)(Cll + (size_t)m * N + col) =
                        pk2h(v0 - __half2float(h0), v1 - __half2float(h1));
                }
            }
        }
    }
}

// ---------------- HMMA fp16 flash attention ----------------
// grid (S/64, H, B), 128 threads (4 warps). Warp w owns queries w*16..+15.
__global__ __launch_bounds__(128) void attn_hmma(
    const __half* __restrict__ qkvh,
    __half* __restrict__ oh, __half* __restrict__ ol)
{
    __shared__ __align__(128) char smem[24576];  // Q 8KB | K 8KB | V 8KB
    uint32_t sb = smem_u32(smem);
    const uint32_t qs = sb, ks = sb + 8192, vs = sb + 16384;

    const int qt = blockIdx.x;
    const int h  = blockIdx.y;
    const int b  = blockIdx.z;
    const int tid = threadIdx.x;
    const int warp = tid >> 5;
    const int lane = tid & 31;

    // load Q tile (scaled by HD^-0.5 = 0.125, exact power of two in fp16)
    const __half2 qscale = __floats2half2_rn(0.125f, 0.125f);
    for (int idx = tid; idx < 1024; idx += 128) {
        int row = idx >> 4, c4 = (idx & 15) * 4;
        const __half* p = qkvh + (size_t)(b * SS + qt * 64 + row) * (3 * DD) + h * 192 + c4;
        uint2 v = *(const uint2*)p;
        __half2* vh = (__half2*)&v;
        vh[0] = __hmul2(vh[0], qscale);
        vh[1] = __hmul2(vh[1], qscale);
        *(uint2*)(smem + swz((uint32_t)(row * 128 + c4 * 2))) = v;
    }
    __syncthreads();

    const int lr8  = lane & 7;
    const int radd = ((lane >> 3) & 1) * 8;
    const int cadd = (lane >> 4) * 16;
    const int arow = warp * 16 + lr8 + radd;

    uint32_t qa[4][4];
#pragma unroll
    for (int kk = 0; kk < 4; kk++)
        ldsm4(qs + swz((uint32_t)(arow * 128 + kk * 32 + cadd)), qa[kk]);

    float o[8][4];
#pragma unroll
    for (int f = 0; f < 8; f++)
#pragma unroll
        for (int j = 0; j < 4; j++) o[f][j] = 0.f;
    float m0v = -1e30f, m1v = -1e30f, l0 = 0.f, l1 = 0.f;
    const int rq0 = qt * 64 + warp * 16 + (lane >> 2);

    for (int kt = 0; kt <= qt; kt++) {
        __syncthreads();
        for (int idx = tid; idx < 1024; idx += 128) {
            int row = idx >> 4, c4 = (idx & 15) * 4;
            const __half* base = qkvh + (size_t)(b * SS + kt * 64 + row) * (3 * DD) + h * 192;
            uint32_t so = swz((uint32_t)(row * 128 + c4 * 2));
            *(uint2*)(smem + 8192 + so)  = *(const uint2*)(base + 64 + c4);
            *(uint2*)(smem + 16384 + so) = *(const uint2*)(base + 128 + c4);
        }
        __syncthreads();

        float s[8][4];
#pragma unroll
        for (int f = 0; f < 8; f++)
#pragma unroll
            for (int j = 0; j < 4; j++) s[f][j] = 0.f;
#pragma unroll
        for (int kk = 0; kk < 4; kk++) {
            int cb = kk * 32 + cadd;
            uint32_t bf[4][4];
#pragma unroll
            for (int n2 = 0; n2 < 4; n2++)
                ldsm4(ks + swz((uint32_t)((n2 * 16 + lr8 + radd) * 128 + cb)), bf[n2]);
#pragma unroll
            for (int ni = 0; ni < 8; ni++)
                mma_f16(s[ni], qa[kk], bf[ni >> 1][ni & 1], bf[ni >> 1][(ni & 1) + 2]);
        }

        if (kt == qt) {
#pragma unroll
            for (int f = 0; f < 8; f++)
#pragma unroll
                for (int j = 0; j < 4; j++) {
                    int kc = kt * 64 + f * 8 + (lane & 3) * 2 + (j & 1);
                    int rr = rq0 + ((j >= 2) ? 8 : 0);
                    if (kc > rr) s[f][j] = -1e30f;
                }
        }

        float tm0 = -1e30f, tm1 = -1e30f;
#pragma unroll
        for (int f = 0; f < 8; f++) {
            tm0 = fmaxf(tm0, fmaxf(s[f][0], s[f][1]));
            tm1 = fmaxf(tm1, fmaxf(s[f][2], s[f][3]));
        }
        tm0 = fmaxf(tm0, __shfl_xor_sync(0xffffffffu, tm0, 1));
        tm0 = fmaxf(tm0, __shfl_xor_sync(0xffffffffu, tm0, 2));
        tm1 = fmaxf(tm1, __shfl_xor_sync(0xffffffffu, tm1, 1));
        tm1 = fmaxf(tm1, __shfl_xor_sync(0xffffffffu, tm1, 2));
        float nm0 = fmaxf(m0v, tm0), nm1 = fmaxf(m1v, tm1);
        float f0 = __expf(m0v - nm0), f1 = __expf(m1v - nm1);
        float ts0 = 0.f, ts1 = 0.f;
#pragma unroll
        for (int f = 0; f < 8; f++) {
            s[f][0] = __expf(s[f][0] - nm0);
            s[f][1] = __expf(s[f][1] - nm0);
            s[f][2] = __expf(s[f][2] - nm1);
            s[f][3] = __expf(s[f][3] - nm1);
            ts0 += s[f][0] + s[f][1];
            ts1 += s[f][2] + s[f][3];
        }
        ts0 += __shfl_xor_sync(0xffffffffu, ts0, 1);
        ts0 += __shfl_xor_sync(0xffffffffu, ts0, 2);
        ts1 += __shfl_xor_sync(0xffffffffu, ts1, 1);
        ts1 += __shfl_xor_sync(0xffffffffu, ts1, 2);
        l0 = l0 * f0 + ts0; l1 = l1 * f1 + ts1;
        m0v = nm0; m1v = nm1;
#pragma unroll
        for (int f = 0; f < 8; f++) {
            o[f][0] *= f0; o[f][1] *= f0; o[f][2] *= f1; o[f][3] *= f1;
        }

        uint32_t pa[4][4];
#pragma unroll
        for (int kk = 0; kk < 4; kk++) {
            pa[kk][0] = pk2h(s[2 * kk][0],     s[2 * kk][1]);
            pa[kk][1] = pk2h(s[2 * kk][2],     s[2 * kk][3]);
            pa[kk][2] = pk2h(s[2 * kk + 1][0], s[2 * kk + 1][1]);
            pa[kk][3] = pk2h(s[2 * kk + 1][2], s[2 * kk + 1][3]);
        }
#pragma unroll
        for (int kk = 0; kk < 4; kk++) {
            uint32_t vbf[4][4];
#pragma unroll
            for (int ng = 0; ng < 4; ng++)
                ldsm4t(vs + swz((uint32_t)((kk * 16 + lr8 + radd) * 128 + ng * 32 + cadd)), vbf[ng]);
#pragma unroll
            for (int ni = 0; ni < 8; ni++)
                mma_f16(o[ni], pa[kk], vbf[ni >> 1][(ni & 1) * 2], vbf[ni >> 1][(ni & 1) * 2 + 1]);
        }
    }

    float il0 = 1.f / l0, il1 = 1.f / l1;
    const int row0 = b * SS + rq0;
#pragma unroll
    for (int f = 0; f < 8; f++) {
        int col = h * 64 + f * 8 + (lane & 3) * 2;
        float v0 = o[f][0] * il0, v1 = o[f][1] * il0;
        float v2 = o[f][2] * il1, v3 = o[f][3] * il1;
        __half h0 = __float2half_rn(v0), h1 = __float2half_rn(v1);
        __half h2 = __float2half_rn(v2), h3 = __float2half_rn(v3);
        size_t p0 = (size_t)row0 * DD + col;
        size_t p1 = (size_t)(row0 + 8) * DD + col;
        *(uint32_t*)(oh + p0) = (uint32_t)__half_as_ushort(h0) | ((uint32_t)__half_as_ushort(h1) << 16);
        *(uint32_t*)(ol + p0) = pk2h(v0 - __half2float(h0), v1 - __half2float(h1));
        *(uint32_t*)(oh + p1) = (uint32_t)__half_as_ushort(h2) | ((uint32_t)__half_as_ushort(h3) << 16);
        *(uint32_t*)(ol + p1) = pk2h(v2 - __half2float(h2), v3 - __half2float(h3));
    }
}

// ---------------- launch ----------------
extern "C" void kernel_launch(void* const* d_in, const int* in_sizes, int n_in,
                              void* d_out, int out_size)
{
    const int*   idx     = (const int*)d_in[0];
    const float* tok_emb = (const float*)d_in[1];
    const float* pos_emb = (const float*)d_in[2];
    const float* qkv_w   = (const float*)d_in[3];
    const float* proj_w  = (const float*)d_in[4];
    const float* proj_b  = (const float*)d_in[5];
    const float* ln1_g   = (const float*)d_in[6];
    const float* ln1_b   = (const float*)d_in[7];
    const float* ln2_g   = (const float*)d_in[8];
    const float* ln2_b   = (const float*)d_in[9];
    const float* w1      = (const float*)d_in[10];
    const float* b1      = (const float*)d_in[11];
    const float* w2      = (const float*)d_in[12];
    const float* b2      = (const float*)d_in[13];
    const float* lnf_g   = (const float*)d_in[14];
    const float* lnf_b   = (const float*)d_in[15];
    const float* head_w  = (const float*)d_in[16];
    const float* head_b  = (const float*)d_in[17];
    float* out = (float*)d_out;

    float* x;
    __half *qkvh, *lnh, *lnl, *ah, *al, *ffh, *ffl, *w;
    cudaGetSymbolAddress((void**)&x, g_x);
    cudaGetSymbolAddress((void**)&qkvh, g_qkvh);
    cudaGetSymbolAddress((void**)&lnh, g_lnh);
    cudaGetSymbolAddress((void**)&lnl, g_lnl);
    cudaGetSymbolAddress((void**)&ah, g_ah);
    cudaGetSymbolAddress((void**)&al, g_al);
    cudaGetSymbolAddress((void**)&ffh, g_ffh);
    cudaGetSymbolAddress((void**)&ffl, g_ffl);
    cudaGetSymbolAddress((void**)&w, g_w);

    cudaFuncSetAttribute(gemm_tc, cudaFuncAttributeMaxDynamicSharedMemorySize, SMEM_GEMM);

    // round all weights to single fp16
    split_half_kernel<<<NQKV / 1024, 256>>>((const float4*)qkv_w, (uint2*)(w + OFF_QKV), NQKV / 4);
    split_half_kernel<<<NPROJ / 1024, 256>>>((const float4*)proj_w, (uint2*)(w + OFF_PROJ), NPROJ / 4);
    split_half_kernel<<<NW1 / 1024, 256>>>((const float4*)w1, (uint2*)(w + OFF_W1), NW1 / 4);
    split_half_kernel<<<NW2 / 1024, 256>>>((const float4*)w2, (uint2*)(w + OFF_W2), NW2 / 4);
    split_half_kernel<<<NHEAD / 1024, 256>>>((const float4*)head_w, (uint2*)(w + OFF_HEAD), NHEAD / 4);

    embed_kernel<<<NTOK, 256>>>(idx, tok_emb, pos_emb, x);

    for (int l = 0; l < LL; l++) {
        // ln1 -> qkv (fp16 out for attention)
        ln_kernel<<<NTOK, 256>>>(x, ln1_g + l * DD, ln1_b + l * DD, lnh, lnl);
        gemm_tc<<<dim3(32, 24), 256, SMEM_GEMM>>>(
            lnh, lnl, w + OFF_QKV + (size_t)l * 3 * DD * DD,
            nullptr, nullptr, nullptr, qkvh, nullptr, nullptr, NTOK, 3 * DD, DD, 0);
        // attention (HMMA flash) -> split fp16 output
        attn_hmma<<<dim3(SS / 64, HH, BB), 128>>>(qkvh, ah, al);
        // proj + residual (fp32 x)
        gemm_tc<<<dim3(32, 8), 256, SMEM_GEMM>>>(
            ah, al, w + OFF_PROJ + (size_t)l * DD * DD,
            proj_b + l * DD, x, x, nullptr, nullptr, nullptr, NTOK, DD, DD, 0);
        // ln2 -> MLP
        ln_kernel<<<NTOK, 256>>>(x, ln2_g + l * DD, ln2_b + l * DD, lnh, lnl);
        gemm_tc<<<dim3(32, 32), 256, SMEM_GEMM>>>(
            lnh, lnl, w + OFF_W1 + (size_t)l * FF_DIM * DD,
            b1 + l * FF_DIM, nullptr, nullptr, nullptr, ffh, ffl, NTOK, FF_DIM, DD, 1);
        gemm_tc<<<dim3(32, 8), 256, SMEM_GEMM>>>(
            ffh, ffl, w + OFF_W2 + (size_t)l * DD * FF_DIM,
            b2 + l * DD, x, x, nullptr, nullptr, nullptr, NTOK, DD, FF_DIM, 0);
    }

    // final LN + LM head
    ln_kernel<<<NTOK, 256>>>(x, lnf_g, lnf_b, lnh, lnl);
    gemm_tc<<<dim3(32, VV / 128), 256, SMEM_GEMM>>>(
        lnh, lnl, w + OFF_HEAD,
        head_b, nullptr, out, nullptr, nullptr, nullptr, NTOK, VV, DD, 0);
}

// round 13
// speedup vs baseline: 5.8538x; 1.0205x over previous
#include <cuda_runtime.h>
#include <cuda_bf16.h>
#include <cuda_fp16.h>
#include <math.h>
#include <stdint.h>

// Model dims
#define BB 4
#define SS 1024
#define VV 32000
#define DD 1024
#define HH 16
#define HD 64
#define LL 8
#define FF_DIM 4096
#define NTOK (BB * SS)   // 4096

// Weight element counts / offsets inside the fp16 weight buffer
#define NQKV   25165824
#define NPROJ  8388608
#define NW1    33554432
#define NW2    33554432
#define NHEAD  32768000
#define OFF_QKV  0
#define OFF_PROJ 25165824
#define OFF_W1   33554432
#define OFF_W2   67108864
#define OFF_HEAD 100663296
#define TOTW     133431296

// stage: Ah 16KB + Al 16KB + B 16KB = 48KB; 2 stages = 96KB (2 CTAs/SM)
#define STAGE_BYTES 49152
#define SMEM_GEMM (1024 + 2 * STAGE_BYTES)

// ---------------- scratch (device globals; no allocation) ----------------
__device__ float g_x[NTOK * DD];          // residual stream (fp32)
__device__ __half g_qkvh[NTOK * 3 * DD];  // qkv projection (fp16, attn input)
__device__ __half g_lnh[NTOK * DD], g_lnl[NTOK * DD];
__device__ __half g_ah [NTOK * DD], g_al [NTOK * DD];
__device__ __half g_ffh[NTOK * FF_DIM], g_ffl[NTOK * FF_DIM];
__device__ __half g_w[TOTW];              // all weights, single fp16

// ---------------- PTX helpers (baseline ISA only) ----------------
__device__ __forceinline__ uint32_t smem_u32(const void* p) {
    uint32_t a;
    asm("{ .reg .u64 t; cvta.to.shared.u64 t, %1; cvt.u32.u64 %0, t; }" : "=r"(a) : "l"(p));
    return a;
}
__device__ __forceinline__ void cp16(uint32_t s, const void* g) {
    asm volatile("cp.async.cg.shared.global [%0], [%1], 16;" :: "r"(s), "l"(g) : "memory");
}
__device__ __forceinline__ void cp_commit() { asm volatile("cp.async.commit_group;" ::: "memory"); }
__device__ __forceinline__ void cp_wait0()  { asm volatile("cp.async.wait_group 0;" ::: "memory"); }
__device__ __forceinline__ void cp_wait1()  { asm volatile("cp.async.wait_group 1;" ::: "memory"); }

__device__ __forceinline__ void ldsm4(uint32_t addr, uint32_t* r) {
    asm volatile("ldmatrix.sync.aligned.m8n8.x4.shared.b16 {%0,%1,%2,%3}, [%4];"
        : "=r"(r[0]), "=r"(r[1]), "=r"(r[2]), "=r"(r[3]) : "r"(addr));
}
__device__ __forceinline__ void ldsm4t(uint32_t addr, uint32_t* r) {
    asm volatile("ldmatrix.sync.aligned.m8n8.x4.trans.shared.b16 {%0,%1,%2,%3}, [%4];"
        : "=r"(r[0]), "=r"(r[1]), "=r"(r[2]), "=r"(r[3]) : "r"(addr));
}
__device__ __forceinline__ void mma_f16(float* c, const uint32_t* a, uint32_t b0, uint32_t b1) {
    asm volatile(
        "mma.sync.aligned.m16n8k16.row.col.f32.f16.f16.f32 "
        "{%0,%1,%2,%3}, {%4,%5,%6,%7}, {%8,%9}, {%0,%1,%2,%3};"
        : "+f"(c[0]), "+f"(c[1]), "+f"(c[2]), "+f"(c[3])
        : "r"(a[0]), "r"(a[1]), "r"(a[2]), "r"(a[3]), "r"(b0), "r"(b1));
}
__device__ __forceinline__ uint32_t swz(uint32_t off) { return off ^ ((off >> 3) & 0x70); }

__device__ __forceinline__ uint32_t pk2h(float a, float b) {
    __half2 h = __floats2half2_rn(a, b);
    return *(uint32_t*)&h;
}

// ---------------- fused weight round: fp32 -> single fp16, all 5 tensors ----------------
__global__ __launch_bounds__(256) void split_all_kernel(
    const float4* __restrict__ qkv_w, const float4* __restrict__ proj_w,
    const float4* __restrict__ w1, const float4* __restrict__ w2,
    const float4* __restrict__ head_w, uint2* __restrict__ out)
{
    long i = (long)blockIdx.x * 256 + threadIdx.x;   // unit = 4 floats
    if (i >= (long)(TOTW / 4)) return;
    const float4* src;
    long off;
    if (i < (long)(OFF_PROJ / 4))      { src = qkv_w;  off = i; }
    else if (i < (long)(OFF_W1 / 4))   { src = proj_w; off = i - OFF_PROJ / 4; }
    else if (i < (long)(OFF_W2 / 4))   { src = w1;     off = i - OFF_W1 / 4; }
    else if (i < (long)(OFF_HEAD / 4)) { src = w2;     off = i - OFF_W2 / 4; }
    else                               { src = head_w; off = i - OFF_HEAD / 4; }
    float4 v = src[off];
    uint2 hv;
    hv.x = pk2h(v.x, v.y); hv.y = pk2h(v.z, v.w);
    out[i] = hv;
}

// ---------------- embedding ----------------
__global__ __launch_bounds__(256) void embed_kernel(
    const int* __restrict__ idx, const float* __restrict__ tok,
    const float* __restrict__ pos, float* __restrict__ x)
{
    int t = blockIdx.x;
    int s = t & (SS - 1);
    int token = idx[t];
    const float4* te = (const float4*)(tok + (size_t)token * DD);
    const float4* pe = (const float4*)(pos + (size_t)s * DD);
    float4* xr = (float4*)(x + (size_t)t * DD);
    int d = threadIdx.x;
    float4 a = te[d], b = pe[d];
    xr[d] = make_float4(a.x + b.x, a.y + b.y, a.z + b.z, a.w + b.w);
}

// ---------------- layernorm -> split fp16 hi/lo ----------------
__global__ __launch_bounds__(256) void ln_kernel(
    const float* __restrict__ x, const float* __restrict__ gw,
    const float* __restrict__ bw, __half* __restrict__ yh,
    __half* __restrict__ yl)
{
    __shared__ float rs[8], rq[8];
    int row = blockIdx.x;
    const float4* xr = (const float4*)(x + (size_t)row * DD);
    float4 v = xr[threadIdx.x];
    float sum = v.x + v.y + v.z + v.w;
    float sq = v.x * v.x + v.y * v.y + v.z * v.z + v.w * v.w;
#pragma unroll
    for (int o = 16; o; o >>= 1) {
        sum += __shfl_xor_sync(0xffffffffu, sum, o);
        sq  += __shfl_xor_sync(0xffffffffu, sq, o);
    }
    int warp = threadIdx.x >> 5;
    if ((threadIdx.x & 31) == 0) { rs[warp] = sum; rq[warp] = sq; }
    __syncthreads();
    float ts = 0.f, tq = 0.f;
#pragma unroll
    for (int w = 0; w < 8; w++) { ts += rs[w]; tq += rq[w]; }
    float mu = ts * (1.f / DD);
    float var = tq * (1.f / DD) - mu * mu;
    float inv = rsqrtf(var + 1e-5f);
    float4 g = ((const float4*)gw)[threadIdx.x];
    float4 bb = ((const float4*)bw)[threadIdx.x];
    float y0 = (v.x - mu) * inv * g.x + bb.x;
    float y1 = (v.y - mu) * inv * g.y + bb.y;
    float y2 = (v.z - mu) * inv * g.z + bb.z;
    float y3 = (v.w - mu) * inv * g.w + bb.w;
    __half h0 = __float2half_rn(y0), h1 = __float2half_rn(y1);
    __half h2 = __float2half_rn(y2), h3 = __float2half_rn(y3);
    uint2 hv, lv;
    hv.x = (uint32_t)__half_as_ushort(h0) | ((uint32_t)__half_as_ushort(h1) << 16);
    hv.y = (uint32_t)__half_as_ushort(h2) | ((uint32_t)__half_as_ushort(h3) << 16);
    lv.x = pk2h(y0 - __half2float(h0), y1 - __half2float(h1));
    lv.y = pk2h(y2 - __half2float(h2), y3 - __half2float(h3));
    ((uint2*)(yh + (size_t)row * DD))[threadIdx.x] = hv;
    ((uint2*)(yl + (size_t)row * DD))[threadIdx.x] = lv;
}

// ---------------- fp16 2-pass mma.sync GEMM ----------------
// C[M,N] = (Ah+Al)[M,K] @ B[N,K]^T   (A fp16 hi/lo, B single fp16)
// CTA tile 128x128, BK=64, 8 warps (2m x 4n), warp tile 64x32, 2 CTAs/SM.
__global__ __launch_bounds__(256, 2) void gemm_tc(
    const __half* __restrict__ Ah, const __half* __restrict__ Al,
    const __half* __restrict__ B,
    const float* __restrict__ bias, const float* __restrict__ res,
    float* __restrict__ Cf, __half* __restrict__ Cs,
    __half* __restrict__ Chh, __half* __restrict__ Cll,
    int M, int N, int K, int silu)
{
    extern __shared__ char smem[];
    const int tid = threadIdx.x;
    const int wid = tid >> 5;
    const int lane = tid & 31;
    const int m0 = blockIdx.x * 128;
    const int n0 = blockIdx.y * 128;
    const int wm = wid & 1;
    const int wn = wid >> 1;

    uint32_t sbase = smem_u32(smem);
    uint32_t tiles = (sbase + 1023) & ~1023u;
    // stage: Ah @0 (16KB), Al @16K (16KB), B @32K (16KB)

    uint32_t swo[4];
    const char *gA[4], *gAl[4], *gB[4];
#pragma unroll
    for (int u = 0; u < 4; u++) {
        int unit = tid + u * 256;
        int row = unit >> 3;
        int cb = (unit & 7) * 16;
        swo[u] = swz((uint32_t)(row * 128 + cb));
        gA[u]  = (const char*)Ah + ((size_t)(m0 + row) * K) * 2 + cb;
        gAl[u] = (const char*)Al + ((size_t)(m0 + row) * K) * 2 + cb;
        gB[u]  = (const char*)B + ((size_t)(n0 + row) * K) * 2 + cb;
    }

    const int lr8  = lane & 7;
    const int radd = ((lane >> 3) & 1) * 8;
    const int cadd = (lane >> 4) * 16;
    const int arow = wm * 64 + lr8 + radd;
    const int brow = wn * 32 + lr8 + radd;

    float acc[64];
#pragma unroll
    for (int i = 0; i < 64; i++) acc[i] = 0.f;

    const int nk = K >> 6;

    {
        uint32_t st = tiles;
#pragma unroll
        for (int u = 0; u < 4; u++) {
            cp16(st + swo[u],         gA[u]);
            cp16(st + 16384 + swo[u], gAl[u]);
            cp16(st + 32768 + swo[u], gB[u]);
        }
        cp_commit(); cp_wait0();
    }
    __syncthreads();

    for (int kc = 0; kc < nk; kc++) {
        int b = kc & 1;
        uint32_t st = tiles + (uint32_t)b * STAGE_BYTES;

        if (kc + 1 < nk) {
            uint32_t st2 = tiles + (uint32_t)(b ^ 1) * STAGE_BYTES;
            size_t koff = (size_t)(kc + 1) * 128;
#pragma unroll
            for (int u = 0; u < 4; u++) {
                cp16(st2 + swo[u],         gA[u] + koff);
                cp16(st2 + 16384 + swo[u], gAl[u] + koff);
                cp16(st2 + 32768 + swo[u], gB[u] + koff);
            }
            cp_commit();
        }

        uint32_t stA = st, stAl = st + 16384, stB = st + 32768;
#pragma unroll
        for (int ks = 0; ks < 4; ks++) {
            int cb = ks * 32 + cadd;
            uint32_t a4[4][4], b4[2][4];
#pragma unroll
            for (int mi = 0; mi < 4; mi++)
                ldsm4(stA + swz((uint32_t)((arow + mi * 16) * 128 + cb)), a4[mi]);
#pragma unroll
            for (int n2 = 0; n2 < 2; n2++)
                ldsm4(stB + swz((uint32_t)((brow + n2 * 16) * 128 + cb)), b4[n2]);
            // pass 1: Ah*B
#pragma unroll
            for (int mi = 0; mi < 4; mi++)
#pragma unroll
                for (int ni = 0; ni < 4; ni++)
                    mma_f16(&acc[(mi * 4 + ni) * 4], a4[mi],
                            b4[ni >> 1][ni & 1], b4[ni >> 1][(ni & 1) + 2]);
            // pass 2: Al*B
#pragma unroll
            for (int mi = 0; mi < 4; mi++)
                ldsm4(stAl + swz((uint32_t)((arow + mi * 16) * 128 + cb)), a4[mi]);
#pragma unroll
            for (int mi = 0; mi < 4; mi++)
#pragma unroll
                for (int ni = 0; ni < 4; ni++)
                    mma_f16(&acc[(mi * 4 + ni) * 4], a4[mi],
                            b4[ni >> 1][ni & 1], b4[ni >> 1][(ni & 1) + 2]);
        }

        if (kc + 1 < nk) cp_wait0();
        __syncthreads();
    }

    // ---------------- epilogue ----------------
    const int r  = lane >> 2;
    const int c2 = (lane & 3) * 2;
#pragma unroll
    for (int mi = 0; mi < 4; mi++) {
#pragma unroll
        for (int ni = 0; ni < 4; ni++) {
            float* cc = &acc[(mi * 4 + ni) * 4];
            int col = n0 + wn * 32 + ni * 8 + c2;
#pragma unroll
            for (int half = 0; half < 2; half++) {
                int m = m0 + wm * 64 + mi * 16 + r + half * 8;
                float v0 = cc[half * 2], v1 = cc[half * 2 + 1];
                if (bias) { v0 += bias[col]; v1 += bias[col + 1]; }
                if (silu) {
                    v0 = v0 / (1.f + __expf(-v0));
                    v1 = v1 / (1.f + __expf(-v1));
                }
                if (res) {
                    v0 += res[(size_t)m * N + col];
                    v1 += res[(size_t)m * N + col + 1];
                }
                if (Cf) *(float2*)(Cf + (size_t)m * N + col) = make_float2(v0, v1);
                if (Cs) *(uint32_t*)(Cs + (size_t)m * N + col) = pk2h(v0, v1);
                if (Chh) {
                    __half h0 = __float2half_rn(v0);
                    __half h1 = __float2half_rn(v1);
                    *(uint32_t*)(Chh + (size_t)m * N + col) =
                        (uint32_t)__half_as_ushort(h0) | ((uint32_t)__half_as_ushort(h1) << 16);
                    *(uint32_t*)(Cll + (size_t)m * N + col) =
                        pk2h(v0 - __half2float(h0), v1 - __half2float(h1));
                }
            }
        }
    }
}

// ---------------- HMMA fp16 flash attention (double-buffered K/V) ----------------
// grid (S/64, H, B), 128 threads (4 warps). Warp w owns queries w*16..+15.
// qt reversed so longest CTAs launch first.
__global__ __launch_bounds__(128) void attn_hmma(
    const __half* __restrict__ qkvh,
    __half* __restrict__ oh, __half* __restrict__ ol)
{
    __shared__ __align__(128) char smem[40960];  // Q 8KB | K0 8KB | V0 8KB | K1 8KB | V1 8KB
    uint32_t sb = smem_u32(smem);
    const uint32_t qs = sb;

    const int qt = (int)gridDim.x - 1 - (int)blockIdx.x;   // reversed: long CTAs first
    const int h  = blockIdx.y;
    const int b  = blockIdx.z;
    const int tid = threadIdx.x;
    const int warp = tid >> 5;
    const int lane = tid & 31;

    // load Q tile (scaled by HD^-0.5 = 0.125, exact power of two in fp16)
    const __half2 qscale = __floats2half2_rn(0.125f, 0.125f);
    for (int idx = tid; idx < 1024; idx += 128) {
        int row = idx >> 4, c4 = (idx & 15) * 4;
        const __half* p = qkvh + (size_t)(b * SS + qt * 64 + row) * (3 * DD) + h * 192 + c4;
        uint2 v = *(const uint2*)p;
        __half2* vh = (__half2*)&v;
        vh[0] = __hmul2(vh[0], qscale);
        vh[1] = __hmul2(vh[1], qscale);
        *(uint2*)(smem + swz((uint32_t)(row * 128 + c4 * 2))) = v;
    }

    // K/V tile loader: 512 16B-units per 8KB tile, 4 per thread, via cp.async
    auto load_kv = [&](int kt, int stg) {
        uint32_t kd = sb + 8192 + (uint32_t)stg * 16384;
        uint32_t vd = kd + 8192;
#pragma unroll
        for (int u = 0; u < 4; u++) {
            int unit = tid + u * 128;           // 0..511
            int row = unit >> 3;
            int cb = (unit & 7) * 16;
            const char* src = (const char*)(qkvh + (size_t)(b * SS + kt * 64 + row) * (3 * DD) + h * 192);
            uint32_t so = swz((uint32_t)(row * 128 + cb));
            cp16(kd + so, src + 128 + cb);
            cp16(vd + so, src + 256 + cb);
        }
        cp_commit();
    };

    load_kv(0, 0);

    const int lr8  = lane & 7;
    const int radd = ((lane >> 3) & 1) * 8;
    const int cadd = (lane >> 4) * 16;
    const int arow = warp * 16 + lr8 + radd;

    __syncthreads();
    uint32_t qa[4][4];
#pragma unroll
    for (int kk = 0; kk < 4; kk++)
        ldsm4(qs + swz((uint32_t)(arow * 128 + kk * 32 + cadd)), qa[kk]);

    float o[8][4];
#pragma unroll
    for (int f = 0; f < 8; f++)
#pragma unroll
        for (int j = 0; j < 4; j++) o[f][j] = 0.f;
    float m0v = -1e30f, m1v = -1e30f, l0 = 0.f, l1 = 0.f;
    const int rq0 = qt * 64 + warp * 16 + (lane >> 2);

    for (int kt = 0; kt <= qt; kt++) {
        int stg = kt & 1;
        if (kt < qt) { load_kv(kt + 1, stg ^ 1); cp_wait1(); }
        else cp_wait0();
        __syncthreads();
        const uint32_t ks = sb + 8192 + (uint32_t)stg * 16384;
        const uint32_t vs = ks + 8192;

        float s[8][4];
#pragma unroll
        for (int f = 0; f < 8; f++)
#pragma unroll
            for (int j = 0; j < 4; j++) s[f][j] = 0.f;
#pragma unroll
        for (int kk = 0; kk < 4; kk++) {
            int cb = kk * 32 + cadd;
            uint32_t bf[4][4];
#pragma unroll
            for (int n2 = 0; n2 < 4; n2++)
                ldsm4(ks + swz((uint32_t)((n2 * 16 + lr8 + radd) * 128 + cb)), bf[n2]);
#pragma unroll
            for (int ni = 0; ni < 8; ni++)
                mma_f16(s[ni], qa[kk], bf[ni >> 1][ni & 1], bf[ni >> 1][(ni & 1) + 2]);
        }

        if (kt == qt) {
#pragma unroll
            for (int f = 0; f < 8; f++)
#pragma unroll
                for (int j = 0; j < 4; j++) {
                    int kc = kt * 64 + f * 8 + (lane & 3) * 2 + (j & 1);
                    int rr = rq0 + ((j >= 2) ? 8 : 0);
                    if (kc > rr) s[f][j] = -1e30f;
                }
        }

        float tm0 = -1e30f, tm1 = -1e30f;
#pragma unroll
        for (int f = 0; f < 8; f++) {
            tm0 = fmaxf(tm0, fmaxf(s[f][0], s[f][1]));
            tm1 = fmaxf(tm1, fmaxf(s[f][2], s[f][3]));
        }
        tm0 = fmaxf(tm0, __shfl_xor_sync(0xffffffffu, tm0, 1));
        tm0 = fmaxf(tm0, __shfl_xor_sync(0xffffffffu, tm0, 2));
        tm1 = fmaxf(tm1, __shfl_xor_sync(0xffffffffu, tm1, 1));
        tm1 = fmaxf(tm1, __shfl_xor_sync(0xffffffffu, tm1, 2));
        float nm0 = fmaxf(m0v, tm0), nm1 = fmaxf(m1v, tm1);
        float f0 = __expf(m0v - nm0), f1 = __expf(m1v - nm1);
        float ts0 = 0.f, ts1 = 0.f;
#pragma unroll
        for (int f = 0; f < 8; f++) {
            s[f][0] = __expf(s[f][0] - nm0);
            s[f][1] = __expf(s[f][1] - nm0);
            s[f][2] = __expf(s[f][2] - nm1);
            s[f][3] = __expf(s[f][3] - nm1);
            ts0 += s[f][0] + s[f][1];
            ts1 += s[f][2] + s[f][3];
        }
        ts0 += __shfl_xor_sync(0xffffffffu, ts0, 1);
        ts0 += __shfl_xor_sync(0xffffffffu, ts0, 2);
        ts1 += __shfl_xor_sync(0xffffffffu, ts1, 1);
        ts1 += __shfl_xor_sync(0xffffffffu, ts1, 2);
        l0 = l0 * f0 + ts0; l1 = l1 * f1 + ts1;
        m0v = nm0; m1v = nm1;
#pragma unroll
        for (int f = 0; f < 8; f++) {
            o[f][0] *= f0; o[f][1] *= f0; o[f][2] *= f1; o[f][3] *= f1;
        }

        uint32_t pa[4][4];
#pragma unroll
        for (int kk = 0; kk < 4; kk++) {
            pa[kk][0] = pk2h(s[2 * kk][0],     s[2 * kk][1]);
            pa[kk][1] = pk2h(s[2 * kk][2],     s[2 * kk][3]);
            pa[kk][2] = pk2h(s[2 * kk + 1][0], s[2 * kk + 1][1]);
            pa[kk][3] = pk2h(s[2 * kk + 1][2], s[2 * kk + 1][3]);
        }
#pragma unroll
        for (int kk = 0; kk < 4; kk++) {
            uint32_t vbf[4][4];
#pragma unroll
            for (int ng = 0; ng < 4; ng++)
                ldsm4t(vs + swz((uint32_t)((kk * 16 + lr8 + radd) * 128 + ng * 32 + cadd)), vbf[ng]);
#pragma unroll
            for (int ni = 0; ni < 8; ni++)
                mma_f16(o[ni], pa[kk], vbf[ni >> 1][(ni & 1) * 2], vbf[ni >> 1][(ni & 1) * 2 + 1]);
        }
        __syncthreads();   // stage consumed; safe to overwrite next iteration
    }

    float il0 = 1.f / l0, il1 = 1.f / l1;
    const int row0 = b * SS + rq0;
#pragma unroll
    for (int f = 0; f < 8; f++) {
        int col = h * 64 + f * 8 + (lane & 3) * 2;
        float v0 = o[f][0] * il0, v1 = o[f][1] * il0;
        float v2 = o[f][2] * il1, v3 = o[f][3] * il1;
        __half h0 = __float2half_rn(v0), h1 = __float2half_rn(v1);
        __half h2 = __float2half_rn(v2), h3 = __float2half_rn(v3);
        size_t p0 = (size_t)row0 * DD + col;
        size_t p1 = (size_t)(row0 + 8) * DD + col;
        *(uint32_t*)(oh + p0) = (uint32_t)__half_as_ushort(h0) | ((uint32_t)__half_as_ushort(h1) << 16);
        *(uint32_t*)(ol + p0) = pk2h(v0 - __half2float(h0), v1 - __half2float(h1));
        *(uint32_t*)(oh + p1) = (uint32_t)__half_as_ushort(h2) | ((uint32_t)__half_as_ushort(h3) << 16);
        *(uint32_t*)(ol + p1) = pk2h(v2 - __half2float(h2), v3 - __half2float(h3));
    }
}

// ---------------- launch ----------------
extern "C" void kernel_launch(void* const* d_in, const int* in_sizes, int n_in,
                              void* d_out, int out_size)
{
    const int*   idx     = (const int*)d_in[0];
    const float* tok_emb = (const float*)d_in[1];
    const float* pos_emb = (const float*)d_in[2];
    const float* qkv_w   = (const float*)d_in[3];
    const float* proj_w  = (const float*)d_in[4];
    const float* proj_b  = (const float*)d_in[5];
    const float* ln1_g   = (const float*)d_in[6];
    const float* ln1_b   = (const float*)d_in[7];
    const float* ln2_g   = (const float*)d_in[8];
    const float* ln2_b   = (const float*)d_in[9];
    const float* w1      = (const float*)d_in[10];
    const float* b1      = (const float*)d_in[11];
    const float* w2      = (const float*)d_in[12];
    const float* b2      = (const float*)d_in[13];
    const float* lnf_g   = (const float*)d_in[14];
    const float* lnf_b   = (const float*)d_in[15];
    const float* head_w  = (const float*)d_in[16];
    const float* head_b  = (const float*)d_in[17];
    float* out = (float*)d_out;

    float* x;
    __half *qkvh, *lnh, *lnl, *ah, *al, *ffh, *ffl, *w;
    cudaGetSymbolAddress((void**)&x, g_x);
    cudaGetSymbolAddress((void**)&qkvh, g_qkvh);
    cudaGetSymbolAddress((void**)&lnh, g_lnh);
    cudaGetSymbolAddress((void**)&lnl, g_lnl);
    cudaGetSymbolAddress((void**)&ah, g_ah);
    cudaGetSymbolAddress((void**)&al, g_al);
    cudaGetSymbolAddress((void**)&ffh, g_ffh);
    cudaGetSymbolAddress((void**)&ffl, g_ffl);
    cudaGetSymbolAddress((void**)&w, g_w);

    cudaFuncSetAttribute(gemm_tc, cudaFuncAttributeMaxDynamicSharedMemorySize, SMEM_GEMM);

    // round all weights to single fp16 (one fused launch)
    split_all_kernel<<<(TOTW / 4 + 255) / 256, 256>>>(
        (const float4*)qkv_w, (const float4*)proj_w, (const float4*)w1,
        (const float4*)w2, (const float4*)head_w, (uint2*)w);

    embed_kernel<<<NTOK, 256>>>(idx, tok_emb, pos_emb, x);

    for (int l = 0; l < LL; l++) {
        // ln1 -> qkv (fp16 out for attention)
        ln_kernel<<<NTOK, 256>>>(x, ln1_g + l * DD, ln1_b + l * DD, lnh, lnl);
        gemm_tc<<<dim3(32, 24), 256, SMEM_GEMM>>>(
            lnh, lnl, w + OFF_QKV + (size_t)l * 3 * DD * DD,
            nullptr, nullptr, nullptr, qkvh, nullptr, nullptr, NTOK, 3 * DD, DD, 0);
        // attention (HMMA flash, double-buffered) -> split fp16 output
        attn_hmma<<<dim3(SS / 64, HH, BB), 128>>>(qkvh, ah, al);
        // proj + residual (fp32 x)
        gemm_tc<<<dim3(32, 8), 256, SMEM_GEMM>>>(
            ah, al, w + OFF_PROJ + (size_t)l * DD * DD,
            proj_b + l * DD, x, x, nullptr, nullptr, nullptr, NTOK, DD, DD, 0);
        // ln2 -> MLP
        ln_kernel<<<NTOK, 256>>>(x, ln2_g + l * DD, ln2_b + l * DD, lnh, lnl);
        gemm_tc<<<dim3(32, 32), 256, SMEM_GEMM>>>(
            lnh, lnl, w + OFF_W1 + (size_t)l * FF_DIM * DD,
            b1 + l * FF_DIM, nullptr, nullptr, nullptr, ffh, ffl, NTOK, FF_DIM, DD, 1);
        gemm_tc<<<dim3(32, 8), 256, SMEM_GEMM>>>(
            ffh, ffl, w + OFF_W2 + (size_t)l * DD * FF_DIM,
            b2 + l * DD, x, x, nullptr, nullptr, nullptr, NTOK, DD, FF_DIM, 0);
    }

    // final LN + LM head
    ln_kernel<<<NTOK, 256>>>(x, lnf_g, lnf_b, lnh, lnl);
    gemm_tc<<<dim3(32, VV / 128), 256, SMEM_GEMM>>>(
        lnh, lnl, w + OFF_HEAD,
        head_b, nullptr, out, nullptr, nullptr, nullptr, NTOK, VV, DD, 0);
}

// round 14
// speedup vs baseline: 5.8781x; 1.0042x over previous
#include <cuda_runtime.h>
#include <cuda_bf16.h>
#include <cuda_fp16.h>
#include <math.h>
#include <stdint.h>

// Model dims
#define BB 4
#define SS 1024
#define VV 32000
#define DD 1024
#define HH 16
#define HD 64
#define LL 8
#define FF_DIM 4096
#define NTOK (BB * SS)   // 4096

// Weight element counts / offsets inside the fp16 weight buffer
#define NQKV   25165824
#define NPROJ  8388608
#define NW1    33554432
#define NW2    33554432
#define NHEAD  32768000
#define OFF_QKV  0
#define OFF_PROJ 25165824
#define OFF_W1   33554432
#define OFF_W2   67108864
#define OFF_HEAD 100663296
#define TOTW     133431296

// stage: Ah 16KB + Al 16KB + B 16KB = 48KB; 2 stages = 96KB (2 CTAs/SM)
#define STAGE_BYTES 49152
#define SMEM_GEMM (1024 + 2 * STAGE_BYTES)

// ---------------- scratch (device globals; no allocation) ----------------
__device__ float g_x[NTOK * DD];          // residual stream (fp32)
__device__ __half g_qkvh[NTOK * 3 * DD];  // qkv projection (fp16, attn input)
__device__ __half g_lnh[NTOK * DD], g_lnl[NTOK * DD];
__device__ __half g_ah [NTOK * DD], g_al [NTOK * DD];
__device__ __half g_ffh[NTOK * FF_DIM], g_ffl[NTOK * FF_DIM];
__device__ __half g_w[TOTW];              // all weights, single fp16

// ---------------- PTX helpers (baseline ISA only) ----------------
__device__ __forceinline__ uint32_t smem_u32(const void* p) {
    uint32_t a;
    asm("{ .reg .u64 t; cvta.to.shared.u64 t, %1; cvt.u32.u64 %0, t; }" : "=r"(a) : "l"(p));
    return a;
}
__device__ __forceinline__ void cp16(uint32_t s, const void* g) {
    asm volatile("cp.async.cg.shared.global [%0], [%1], 16;" :: "r"(s), "l"(g) : "memory");
}
__device__ __forceinline__ void cp_commit() { asm volatile("cp.async.commit_group;" ::: "memory"); }
__device__ __forceinline__ void cp_wait0()  { asm volatile("cp.async.wait_group 0;" ::: "memory"); }
__device__ __forceinline__ void cp_wait1()  { asm volatile("cp.async.wait_group 1;" ::: "memory"); }

__device__ __forceinline__ void ldsm4(uint32_t addr, uint32_t* r) {
    asm volatile("ldmatrix.sync.aligned.m8n8.x4.shared.b16 {%0,%1,%2,%3}, [%4];"
        : "=r"(r[0]), "=r"(r[1]), "=r"(r[2]), "=r"(r[3]) : "r"(addr));
}
__device__ __forceinline__ void ldsm4t(uint32_t addr, uint32_t* r) {
    asm volatile("ldmatrix.sync.aligned.m8n8.x4.trans.shared.b16 {%0,%1,%2,%3}, [%4];"
        : "=r"(r[0]), "=r"(r[1]), "=r"(r[2]), "=r"(r[3]) : "r"(addr));
}
__device__ __forceinline__ void mma_f16(float* c, const uint32_t* a, uint32_t b0, uint32_t b1) {
    asm volatile(
        "mma.sync.aligned.m16n8k16.row.col.f32.f16.f16.f32 "
        "{%0,%1,%2,%3}, {%4,%5,%6,%7}, {%8,%9}, {%0,%1,%2,%3};"
        : "+f"(c[0]), "+f"(c[1]), "+f"(c[2]), "+f"(c[3])
        : "r"(a[0]), "r"(a[1]), "r"(a[2]), "r"(a[3]), "r"(b0), "r"(b1));
}
__device__ __forceinline__ uint32_t swz(uint32_t off) { return off ^ ((off >> 3) & 0x70); }

__device__ __forceinline__ uint32_t pk2h(float a, float b) {
    __half2 h = __floats2half2_rn(a, b);
    return *(uint32_t*)&h;
}

// ---------------- fused weight round: fp32 -> single fp16, all 5 tensors ----------------
__global__ __launch_bounds__(256) void split_all_kernel(
    const float4* __restrict__ qkv_w, const float4* __restrict__ proj_w,
    const float4* __restrict__ w1, const float4* __restrict__ w2,
    const float4* __restrict__ head_w, uint2* __restrict__ out)
{
    long i = (long)blockIdx.x * 256 + threadIdx.x;   // unit = 4 floats
    if (i >= (long)(TOTW / 4)) return;
    const float4* src;
    long off;
    if (i < (long)(OFF_PROJ / 4))      { src = qkv_w;  off = i; }
    else if (i < (long)(OFF_W1 / 4))   { src = proj_w; off = i - OFF_PROJ / 4; }
    else if (i < (long)(OFF_W2 / 4))   { src = w1;     off = i - OFF_W1 / 4; }
    else if (i < (long)(OFF_HEAD / 4)) { src = w2;     off = i - OFF_W2 / 4; }
    else                               { src = head_w; off = i - OFF_HEAD / 4; }
    float4 v = src[off];
    uint2 hv;
    hv.x = pk2h(v.x, v.y); hv.y = pk2h(v.z, v.w);
    out[i] = hv;
}

// ---------------- embedding ----------------
__global__ __launch_bounds__(256) void embed_kernel(
    const int* __restrict__ idx, const float* __restrict__ tok,
    const float* __restrict__ pos, float* __restrict__ x)
{
    int t = blockIdx.x;
    int s = t & (SS - 1);
    int token = idx[t];
    const float4* te = (const float4*)(tok + (size_t)token * DD);
    const float4* pe = (const float4*)(pos + (size_t)s * DD);
    float4* xr = (float4*)(x + (size_t)t * DD);
    int d = threadIdx.x;
    float4 a = te[d], b = pe[d];
    xr[d] = make_float4(a.x + b.x, a.y + b.y, a.z + b.z, a.w + b.w);
}

// ---------------- layernorm -> split fp16 hi/lo ----------------
__global__ __launch_bounds__(256) void ln_kernel(
    const float* __restrict__ x, const float* __restrict__ gw,
    const float* __restrict__ bw, __half* __restrict__ yh,
    __half* __restrict__ yl)
{
    __shared__ float rs[8], rq[8];
    int row = blockIdx.x;
    const float4* xr = (const float4*)(x + (size_t)row * DD);
    float4 v = xr[threadIdx.x];
    float sum = v.x + v.y + v.z + v.w;
    float sq = v.x * v.x + v.y * v.y + v.z * v.z + v.w * v.w;
#pragma unroll
    for (int o = 16; o; o >>= 1) {
        sum += __shfl_xor_sync(0xffffffffu, sum, o);
        sq  += __shfl_xor_sync(0xffffffffu, sq, o);
    }
    int warp = threadIdx.x >> 5;
    if ((threadIdx.x & 31) == 0) { rs[warp] = sum; rq[warp] = sq; }
    __syncthreads();
    float ts = 0.f, tq = 0.f;
#pragma unroll
    for (int w = 0; w < 8; w++) { ts += rs[w]; tq += rq[w]; }
    float mu = ts * (1.f / DD);
    float var = tq * (1.f / DD) - mu * mu;
    float inv = rsqrtf(var + 1e-5f);
    float4 g = ((const float4*)gw)[threadIdx.x];
    float4 bb = ((const float4*)bw)[threadIdx.x];
    float y0 = (v.x - mu) * inv * g.x + bb.x;
    float y1 = (v.y - mu) * inv * g.y + bb.y;
    float y2 = (v.z - mu) * inv * g.z + bb.z;
    float y3 = (v.w - mu) * inv * g.w + bb.w;
    __half h0 = __float2half_rn(y0), h1 = __float2half_rn(y1);
    __half h2 = __float2half_rn(y2), h3 = __float2half_rn(y3);
    uint2 hv, lv;
    hv.x = (uint32_t)__half_as_ushort(h0) | ((uint32_t)__half_as_ushort(h1) << 16);
    hv.y = (uint32_t)__half_as_ushort(h2) | ((uint32_t)__half_as_ushort(h3) << 16);
    lv.x = pk2h(y0 - __half2float(h0), y1 - __half2float(h1));
    lv.y = pk2h(y2 - __half2float(h2), y3 - __half2float(h3));
    ((uint2*)(yh + (size_t)row * DD))[threadIdx.x] = hv;
    ((uint2*)(yl + (size_t)row * DD))[threadIdx.x] = lv;
}

// ---------------- fp16 2-pass mma.sync GEMM ----------------
// C[M,N] = (Ah+Al)[M,K] @ B[N,K]^T   (A fp16 hi/lo, B single fp16)
// CTA tile 128x128, BK=64, 8 warps (2m x 4n), warp tile 64x32, 2 CTAs/SM.
// ldsm addresses use the identity swz(row*128+cb) = row*128 + (cb ^ ((row&7)*16))
// -> pure adds inside the loop. Separate hi/lo frag registers kill the WAR hazard.
__global__ __launch_bounds__(256, 2) void gemm_tc(
    const __half* __restrict__ Ah, const __half* __restrict__ Al,
    const __half* __restrict__ B,
    const float* __restrict__ bias, const float* __restrict__ res,
    float* __restrict__ Cf, __half* __restrict__ Cs,
    __half* __restrict__ Chh, __half* __restrict__ Cll,
    int M, int N, int K, int silu)
{
    extern __shared__ char smem[];
    const int tid = threadIdx.x;
    const int wid = tid >> 5;
    const int lane = tid & 31;
    const int m0 = blockIdx.x * 128;
    const int n0 = blockIdx.y * 128;
    const int wm = wid & 1;
    const int wn = wid >> 1;

    uint32_t sbase = smem_u32(smem);
    uint32_t tiles = (sbase + 1023) & ~1023u;
    // stage: Ah @0 (16KB), Al @16K (16KB), B @32K (16KB)

    uint32_t swo[4];
    const char *gA[4], *gAl[4], *gB[4];
#pragma unroll
    for (int u = 0; u < 4; u++) {
        int unit = tid + u * 256;
        int row = unit >> 3;
        int cb = (unit & 7) * 16;
        swo[u] = swz((uint32_t)(row * 128 + cb));
        gA[u]  = (const char*)Ah + ((size_t)(m0 + row) * K) * 2 + cb;
        gAl[u] = (const char*)Al + ((size_t)(m0 + row) * K) * 2 + cb;
        gB[u]  = (const char*)B + ((size_t)(n0 + row) * K) * 2 + cb;
    }

    const int lr8  = lane & 7;
    const int radd = ((lane >> 3) & 1) * 8;
    const int cadd = (lane >> 4) * 16;
    const int arow = wm * 64 + lr8 + radd;
    const int brow = wn * 32 + lr8 + radd;

    // swizzle-free ldsm addressing (mi*16 keeps row&7 invariant)
    const uint32_t abase = (uint32_t)arow * 128;
    const uint32_t xa = (uint32_t)((arow & 7) * 16);
    const uint32_t bbase = (uint32_t)brow * 128;
    const uint32_t xb = (uint32_t)((brow & 7) * 16);

    float acc[64];
#pragma unroll
    for (int i = 0; i < 64; i++) acc[i] = 0.f;

    const int nk = K >> 6;

    {
        uint32_t st = tiles;
#pragma unroll
        for (int u = 0; u < 4; u++) {
            cp16(st + swo[u],         gA[u]);
            cp16(st + 16384 + swo[u], gAl[u]);
            cp16(st + 32768 + swo[u], gB[u]);
        }
        cp_commit(); cp_wait0();
    }
    __syncthreads();

    for (int kc = 0; kc < nk; kc++) {
        int b = kc & 1;
        uint32_t st = tiles + (uint32_t)b * STAGE_BYTES;

        if (kc + 1 < nk) {
            uint32_t st2 = tiles + (uint32_t)(b ^ 1) * STAGE_BYTES;
            size_t koff = (size_t)(kc + 1) * 128;
#pragma unroll
            for (int u = 0; u < 4; u++) {
                cp16(st2 + swo[u],         gA[u] + koff);
                cp16(st2 + 16384 + swo[u], gAl[u] + koff);
                cp16(st2 + 32768 + swo[u], gB[u] + koff);
            }
            cp_commit();
        }

        const uint32_t stA = st, stAl = st + 16384, stB = st + 32768;
#pragma unroll
        for (int ks = 0; ks < 4; ks++) {
            const uint32_t cbk = (uint32_t)(ks * 32) + (uint32_t)cadd;
            const uint32_t ca = abase + (cbk ^ xa);   // + mi*2048 per A frag
            const uint32_t cbb = bbase + (cbk ^ xb);  // + n2*2048 per B frag

            uint32_t bf[2][4];
            ldsm4(stB + cbb, bf[0]);
            ldsm4(stB + cbb + 2048, bf[1]);

            // mi pair 0 (mi = 0,1): hi and lo in separate regs, loaded before MMAs
            uint32_t ah0[4], ah1[4], al0[4], al1[4];
            ldsm4(stA + ca, ah0);
            ldsm4(stA + ca + 2048, ah1);
            ldsm4(stAl + ca, al0);
            ldsm4(stAl + ca + 2048, al1);
#pragma unroll
            for (int ni = 0; ni < 4; ni++) {
                uint32_t b0 = bf[ni >> 1][ni & 1], b1 = bf[ni >> 1][(ni & 1) + 2];
                mma_f16(&acc[(0 * 4 + ni) * 4], ah0, b0, b1);
                mma_f16(&acc[(1 * 4 + ni) * 4], ah1, b0, b1);
                mma_f16(&acc[(0 * 4 + ni) * 4], al0, b0, b1);
                mma_f16(&acc[(1 * 4 + ni) * 4], al1, b0, b1);
            }

            // mi pair 1 (mi = 2,3)
            ldsm4(stA + ca + 4096, ah0);
            ldsm4(stA + ca + 6144, ah1);
            ldsm4(stAl + ca + 4096, al0);
            ldsm4(stAl + ca + 6144, al1);
#pragma unroll
            for (int ni = 0; ni < 4; ni++) {
                uint32_t b0 = bf[ni >> 1][ni & 1], b1 = bf[ni >> 1][(ni & 1) + 2];
                mma_f16(&acc[(2 * 4 + ni) * 4], ah0, b0, b1);
                mma_f16(&acc[(3 * 4 + ni) * 4], ah1, b0, b1);
                mma_f16(&acc[(2 * 4 + ni) * 4], al0, b0, b1);
                mma_f16(&acc[(3 * 4 + ni) * 4], al1, b0, b1);
            }
        }

        if (kc + 1 < nk) cp_wait0();
        __syncthreads();
    }

    // ---------------- epilogue ----------------
    const int r  = lane >> 2;
    const int c2 = (lane & 3) * 2;
#pragma unroll
    for (int mi = 0; mi < 4; mi++) {
#pragma unroll
        for (int ni = 0; ni < 4; ni++) {
            float* cc = &acc[(mi * 4 + ni) * 4];
            int col = n0 + wn * 32 + ni * 8 + c2;
#pragma unroll
            for (int half = 0; half < 2; half++) {
                int m = m0 + wm * 64 + mi * 16 + r + half * 8;
                float v0 = cc[half * 2], v1 = cc[half * 2 + 1];
                if (bias) { v0 += bias[col]; v1 += bias[col + 1]; }
                if (silu) {
                    v0 = v0 / (1.f + __expf(-v0));
                    v1 = v1 / (1.f + __expf(-v1));
                }
                if (res) {
                    v0 += res[(size_t)m * N + col];
                    v1 += res[(size_t)m * N + col + 1];
                }
                if (Cf) *(float2*)(Cf + (size_t)m * N + col) = make_float2(v0, v1);
                if (Cs) *(uint32_t*)(Cs + (size_t)m * N + col) = pk2h(v0, v1);
                if (Chh) {
                    __half h0 = __float2half_rn(v0);
                    __half h1 = __float2half_rn(v1);
                    *(uint32_t*)(Chh + (size_t)m * N + col) =
                        (uint32_t)__half_as_ushort(h0) | ((uint32_t)__half_as_ushort(h1) << 16);
                    *(uint32_t*)(Cll + (size_t)m * N + col) =
                        pk2h(v0 - __half2float(h0), v1 - __half2float(h1));
                }
            }
        }
    }
}

// ---------------- HMMA fp16 flash attention (double-buffered K/V) ----------------
// grid (S/64, H, B), 128 threads (4 warps). Warp w owns queries w*16..+15.
// qt reversed so longest CTAs launch first.
__global__ __launch_bounds__(128) void attn_hmma(
    const __half* __restrict__ qkvh,
    __half* __restrict__ oh, __half* __restrict__ ol)
{
    __shared__ __align__(128) char smem[40960];  // Q 8KB | K0 8KB | V0 8KB | K1 8KB | V1 8KB
    uint32_t sb = smem_u32(smem);
    const uint32_t qs = sb;

    const int qt = (int)gridDim.x - 1 - (int)blockIdx.x;   // reversed: long CTAs first
    const int h  = blockIdx.y;
    const int b  = blockIdx.z;
    const int tid = threadIdx.x;
    const int warp = tid >> 5;
    const int lane = tid & 31;

    // load Q tile (scaled by HD^-0.5 = 0.125, exact power of two in fp16)
    const __half2 qscale = __floats2half2_rn(0.125f, 0.125f);
    for (int idx = tid; idx < 1024; idx += 128) {
        int row = idx >> 4, c4 = (idx & 15) * 4;
        const __half* p = qkvh + (size_t)(b * SS + qt * 64 + row) * (3 * DD) + h * 192 + c4;
        uint2 v = *(const uint2*)p;
        __half2* vh = (__half2*)&v;
        vh[0] = __hmul2(vh[0], qscale);
        vh[1] = __hmul2(vh[1], qscale);
        *(uint2*)(smem + swz((uint32_t)(row * 128 + c4 * 2))) = v;
    }

    // K/V tile loader: 512 16B-units per 8KB tile, 4 per thread, via cp.async
    auto load_kv = [&](int kt, int stg) {
        uint32_t kd = sb + 8192 + (uint32_t)stg * 16384;
        uint32_t vd = kd + 8192;
#pragma unroll
        for (int u = 0; u < 4; u++) {
            int unit = tid + u * 128;           // 0..511
            int row = unit >> 3;
            int cb = (unit & 7) * 16;
            const char* src = (const char*)(qkvh + (size_t)(b * SS + kt * 64 + row) * (3 * DD) + h * 192);
            uint32_t so = swz((uint32_t)(row * 128 + cb));
            cp16(kd + so, src + 128 + cb);
            cp16(vd + so, src + 256 + cb);
        }
        cp_commit();
    };

    load_kv(0, 0);

    const int lr8  = lane & 7;
    const int radd = ((lane >> 3) & 1) * 8;
    const int cadd = (lane >> 4) * 16;
    const int arow = warp * 16 + lr8 + radd;

    __syncthreads();
    uint32_t qa[4][4];
#pragma unroll
    for (int kk = 0; kk < 4; kk++)
        ldsm4(qs + swz((uint32_t)(arow * 128 + kk * 32 + cadd)), qa[kk]);

    float o[8][4];
#pragma unroll
    for (int f = 0; f < 8; f++)
#pragma unroll
        for (int j = 0; j < 4; j++) o[f][j] = 0.f;
    float m0v = -1e30f, m1v = -1e30f, l0 = 0.f, l1 = 0.f;
    const int rq0 = qt * 64 + warp * 16 + (lane >> 2);

    for (int kt = 0; kt <= qt; kt++) {
        int stg = kt & 1;
        if (kt < qt) { load_kv(kt + 1, stg ^ 1); cp_wait1(); }
        else cp_wait0();
        __syncthreads();
        const uint32_t ks = sb + 8192 + (uint32_t)stg * 16384;
        const uint32_t vs = ks + 8192;

        float s[8][4];
#pragma unroll
        for (int f = 0; f < 8; f++)
#pragma unroll
            for (int j = 0; j < 4; j++) s[f][j] = 0.f;
#pragma unroll
        for (int kk = 0; kk < 4; kk++) {
            int cb = kk * 32 + cadd;
            uint32_t bf[4][4];
#pragma unroll
            for (int n2 = 0; n2 < 4; n2++)
                ldsm4(ks + swz((uint32_t)((n2 * 16 + lr8 + radd) * 128 + cb)), bf[n2]);
#pragma unroll
            for (int ni = 0; ni < 8; ni++)
                mma_f16(s[ni], qa[kk], bf[ni >> 1][ni & 1], bf[ni >> 1][(ni & 1) + 2]);
        }

        if (kt == qt) {
#pragma unroll
            for (int f = 0; f < 8; f++)
#pragma unroll
                for (int j = 0; j < 4; j++) {
                    int kc = kt * 64 + f * 8 + (lane & 3) * 2 + (j & 1);
                    int rr = rq0 + ((j >= 2) ? 8 : 0);
                    if (kc > rr) s[f][j] = -1e30f;
                }
        }

        float tm0 = -1e30f, tm1 = -1e30f;
#pragma unroll
        for (int f = 0; f < 8; f++) {
            tm0 = fmaxf(tm0, fmaxf(s[f][0], s[f][1]));
            tm1 = fmaxf(tm1, fmaxf(s[f][2], s[f][3]));
        }
        tm0 = fmaxf(tm0, __shfl_xor_sync(0xffffffffu, tm0, 1));
        tm0 = fmaxf(tm0, __shfl_xor_sync(0xffffffffu, tm0, 2));
        tm1 = fmaxf(tm1, __shfl_xor_sync(0xffffffffu, tm1, 1));
        tm1 = fmaxf(tm1, __shfl_xor_sync(0xffffffffu, tm1, 2));
        float nm0 = fmaxf(m0v, tm0), nm1 = fmaxf(m1v, tm1);
        float f0 = __expf(m0v - nm0), f1 = __expf(m1v - nm1);
        float ts0 = 0.f, ts1 = 0.f;
#pragma unroll
        for (int f = 0; f < 8; f++) {
            s[f][0] = __expf(s[f][0] - nm0);
            s[f][1] = __expf(s[f][1] - nm0);
            s[f][2] = __expf(s[f][2] - nm1);
            s[f][3] = __expf(s[f][3] - nm1);
            ts0 += s[f][0] + s[f][1];
            ts1 += s[f][2] + s[f][3];
        }
        ts0 += __shfl_xor_sync(0xffffffffu, ts0, 1);
        ts0 += __shfl_xor_sync(0xffffffffu, ts0, 2);
        ts1 += __shfl_xor_sync(0xffffffffu, ts1, 1);
        ts1 += __shfl_xor_sync(0xffffffffu, ts1, 2);
        l0 = l0 * f0 + ts0; l1 = l1 * f1 + ts1;
        m0v = nm0; m1v = nm1;
#pragma unroll
        for (int f = 0; f < 8; f++) {
            o[f][0] *= f0; o[f][1] *= f0; o[f][2] *= f1; o[f][3] *= f1;
        }

        uint32_t pa[4][4];
#pragma unroll
        for (int kk = 0; kk < 4; kk++) {
            pa[kk][0] = pk2h(s[2 * kk][0],     s[2 * kk][1]);
            pa[kk][1] = pk2h(s[2 * kk][2],     s[2 * kk][3]);
            pa[kk][2] = pk2h(s[2 * kk + 1][0], s[2 * kk + 1][1]);
            pa[kk][3] = pk2h(s[2 * kk + 1][2], s[2 * kk + 1][3]);
        }
#pragma unroll
        for (int kk = 0; kk < 4; kk++) {
            uint32_t vbf[4][4];
#pragma unroll
            for (int ng = 0; ng < 4; ng++)
                ldsm4t(vs + swz((uint32_t)((kk * 16 + lr8 + radd) * 128 + ng * 32 + cadd)), vbf[ng]);
#pragma unroll
            for (int ni = 0; ni < 8; ni++)
                mma_f16(o[ni], pa[kk], vbf[ni >> 1][(ni & 1) * 2], vbf[ni >> 1][(ni & 1) * 2 + 1]);
        }
        __syncthreads();   // stage consumed; safe to overwrite next iteration
    }

    float il0 = 1.f / l0, il1 = 1.f / l1;
    const int row0 = b * SS + rq0;
#pragma unroll
    for (int f = 0; f < 8; f++) {
        int col = h * 64 + f * 8 + (lane & 3) * 2;
        float v0 = o[f][0] * il0, v1 = o[f][1] * il0;
        float v2 = o[f][2] * il1, v3 = o[f][3] * il1;
        __half h0 = __float2half_rn(v0), h1 = __float2half_rn(v1);
        __half h2 = __float2half_rn(v2), h3 = __float2half_rn(v3);
        size_t p0 = (size_t)row0 * DD + col;
        size_t p1 = (size_t)(row0 + 8) * DD + col;
        *(uint32_t*)(oh + p0) = (uint32_t)__half_as_ushort(h0) | ((uint32_t)__half_as_ushort(h1) << 16);
        *(uint32_t*)(ol + p0) = pk2h(v0 - __half2float(h0), v1 - __half2float(h1));
        *(uint32_t*)(oh + p1) = (uint32_t)__half_as_ushort(h2) | ((uint32_t)__half_as_ushort(h3) << 16);
        *(uint32_t*)(ol + p1) = pk2h(v2 - __half2float(h2), v3 - __half2float(h3));
    }
}

// ---------------- launch ----------------
extern "C" void kernel_launch(void* const* d_in, const int* in_sizes, int n_in,
                              void* d_out, int out_size)
{
    const int*   idx     = (const int*)d_in[0];
    const float* tok_emb = (const float*)d_in[1];
    const float* pos_emb = (const float*)d_in[2];
    const float* qkv_w   = (const float*)d_in[3];
    const float* proj_w  = (const float*)d_in[4];
    const float* proj_b  = (const float*)d_in[5];
    const float* ln1_g   = (const float*)d_in[6];
    const float* ln1_b   = (const float*)d_in[7];
    const float* ln2_g   = (const float*)d_in[8];
    const float* ln2_b   = (const float*)d_in[9];
    const float* w1      = (const float*)d_in[10];
    const float* b1      = (const float*)d_in[11];
    const float* w2      = (const float*)d_in[12];
    const float* b2      = (const float*)d_in[13];
    const float* lnf_g   = (const float*)d_in[14];
    const float* lnf_b   = (const float*)d_in[15];
    const float* head_w  = (const float*)d_in[16];
    const float* head_b  = (const float*)d_in[17];
    float* out = (float*)d_out;

    float* x;
    __half *qkvh, *lnh, *lnl, *ah, *al, *ffh, *ffl, *w;
    cudaGetSymbolAddress((void**)&x, g_x);
    cudaGetSymbolAddress((void**)&qkvh, g_qkvh);
    cudaGetSymbolAddress((void**)&lnh, g_lnh);
    cudaGetSymbolAddress((void**)&lnl, g_lnl);
    cudaGetSymbolAddress((void**)&ah, g_ah);
    cudaGetSymbolAddress((void**)&al, g_al);
    cudaGetSymbolAddress((void**)&ffh, g_ffh);
    cudaGetSymbolAddress((void**)&ffl, g_ffl);
    cudaGetSymbolAddress((void**)&w, g_w);

    cudaFuncSetAttribute(gemm_tc, cudaFuncAttributeMaxDynamicSharedMemorySize, SMEM_GEMM);

    // round all weights to single fp16 (one fused launch)
    split_all_kernel<<<(TOTW / 4 + 255) / 256, 256>>>(
        (const float4*)qkv_w, (const float4*)proj_w, (const float4*)w1,
        (const float4*)w2, (const float4*)head_w, (uint2*)w);

    embed_kernel<<<NTOK, 256>>>(idx, tok_emb, pos_emb, x);

    for (int l = 0; l < LL; l++) {
        // ln1 -> qkv (fp16 out for attention)
        ln_kernel<<<NTOK, 256>>>(x, ln1_g + l * DD, ln1_b + l * DD, lnh, lnl);
        gemm_tc<<<dim3(32, 24), 256, SMEM_GEMM>>>(
            lnh, lnl, w + OFF_QKV + (size_t)l * 3 * DD * DD,
            nullptr, nullptr, nullptr, qkvh, nullptr, nullptr, NTOK, 3 * DD, DD, 0);
        // attention (HMMA flash, double-buffered) -> split fp16 output
        attn_hmma<<<dim3(SS / 64, HH, BB), 128>>>(qkvh, ah, al);
        // proj + residual (fp32 x)
        gemm_tc<<<dim3(32, 8), 256, SMEM_GEMM>>>(
            ah, al, w + OFF_PROJ + (size_t)l * DD * DD,
            proj_b + l * DD, x, x, nullptr, nullptr, nullptr, NTOK, DD, DD, 0);
        // ln2 -> MLP
        ln_kernel<<<NTOK, 256>>>(x, ln2_g + l * DD, ln2_b + l * DD, lnh, lnl);
        gemm_tc<<<dim3(32, 32), 256, SMEM_GEMM>>>(
            lnh, lnl, w + OFF_W1 + (size_t)l * FF_DIM * DD,
            b1 + l * FF_DIM, nullptr, nullptr, nullptr, ffh, ffl, NTOK, FF_DIM, DD, 1);
        gemm_tc<<<dim3(32, 8), 256, SMEM_GEMM>>>(
            ffh, ffl, w + OFF_W2 + (size_t)l * DD * FF_DIM,
            b2 + l * DD, x, x, nullptr, nullptr, nullptr, NTOK, DD, FF_DIM, 0);
    }

    // final LN + LM head
    ln_kernel<<<NTOK, 256>>>(x, lnf_g, lnf_b, lnh, lnl);
    gemm_tc<<<dim3(32, VV / 128), 256, SMEM_GEMM>>>(
        lnh, lnl, w + OFF_HEAD,
        head_b, nullptr, out, nullptr, nullptr, nullptr, NTOK, VV, DD, 0);
}